// round 1
// baseline (speedup 1.0000x reference)
#include <cuda_runtime.h>
#include <math.h>

#define T_  8
#define N_  20000
#define E_  320000
#define DIN 64
#define H_  128
#define EPSB 1e-5f

// ---------- scratch (device globals: no allocation allowed) ----------
__device__ int    g_deg [T_*N_];
__device__ float  g_dinv[T_*N_];
__device__ float  g_w2  [T_*N_];
__device__ float4 g_xa4 [T_*N_*(DIN/4)];     // aggregated x, [t][n][64] as float4
__device__ float  g_S   [T_*H_];             // per-t weighted sum of h1b
__device__ float4 g_WT4 [4][32*512];         // LSTM weights, float4 over k, [k4*512+r]
__device__ float  g_bsum[2][512];            // bih+bhh per layer

// ---------- f32x2 packed helpers ----------
__device__ __forceinline__ unsigned long long pk2(float a, float b) {
    unsigned long long r;
    asm("mov.b64 %0, {%1, %2};" : "=l"(r) : "f"(a), "f"(b));
    return r;
}
__device__ __forceinline__ unsigned long long ffma2(unsigned long long a,
                                                    unsigned long long b,
                                                    unsigned long long c) {
    unsigned long long d;
    asm("fma.rn.f32x2 %0, %1, %2, %3;" : "=l"(d) : "l"(a), "l"(b), "l"(c));
    return d;
}
__device__ __forceinline__ float2 upk2(unsigned long long v) {
    float2 f;
    asm("mov.b64 {%0, %1}, %2;" : "=f"(f.x), "=f"(f.y) : "l"(v));
    return f;
}

// ---------- K1: zero deg + S ----------
__global__ void k_zero() {
    int i = blockIdx.x * blockDim.x + threadIdx.x;
    if (i < T_*N_) g_deg[i] = 0;
    if (i < T_*H_) g_S[i]   = 0.f;
}

// ---------- K2: in-degree count (dst side) ----------
__global__ void k_count(const int* __restrict__ ei) {
    int i = blockIdx.x * blockDim.x + threadIdx.x;
    if (i >= T_*E_) return;
    int t = i / E_, e = i - t*E_;
    int dst = ei[t*2*E_ + E_ + e];
    atomicAdd(&g_deg[t*N_ + dst], 1);
}

// ---------- K3: dinv + w2 self-loop term ----------
__global__ void k_dinv() {
    int i = blockIdx.x * blockDim.x + threadIdx.x;
    if (i >= T_*N_) return;
    float d = rsqrtf(1.0f + (float)g_deg[i]);   // deg includes self-loop
    g_dinv[i] = d;
    g_w2[i]   = d * d;                          // self-loop coef for layer-2 weight
}

// ---------- K4: xa init = self-loop contribution dinv^2 * x ----------
__global__ void k_xainit(const float* __restrict__ x) {
    int i = blockIdx.x * blockDim.x + threadIdx.x;
    if (i >= T_*N_*16) return;
    int node = i >> 4;
    float d = g_dinv[node];
    float c = d * d;
    float4 v = ((const float4*)x)[i];
    g_xa4[i] = make_float4(c*v.x, c*v.y, c*v.z, c*v.w);
}

// ---------- K5: edge scatter (layer-1 agg in input space + layer-2 scalar weights) ----------
__global__ void __launch_bounds__(256) k_scatter(const int* __restrict__ ei,
                                                 const float* __restrict__ x) {
    int i = blockIdx.x * 256 + threadIdx.x;
    if (i >= T_*E_*4) return;
    int chunk = i & 3;
    int idx   = i >> 2;
    int t = idx / E_, e = idx - t*E_;
    int src = ei[t*2*E_ + e];
    int dst = ei[t*2*E_ + E_ + e];
    int ns = t*N_ + src, nd = t*N_ + dst;
    float c = g_dinv[ns] * g_dinv[nd];
    if (chunk == 0) atomicAdd(&g_w2[ns], c);    // layer-2 scalar weight scatters to SRC
    const float4* xs = ((const float4*)x) + (size_t)ns * 16;
    float4*       xd = g_xa4 + (size_t)nd * 16;
#pragma unroll
    for (int u = 0; u < 4; u++) {
        int q = chunk*4 + u;
        float4 v = xs[q];
        asm volatile("red.global.add.v4.f32 [%0], {%1, %2, %3, %4};"
                     :: "l"(xd + q),
                        "f"(c*v.x), "f"(c*v.y), "f"(c*v.z), "f"(c*v.w)
                     : "memory");
    }
}

// ---------- K6: fused (xa @ W1 + b1) -> BN1 -> ReLU -> weighted sum into S[t] ----------
__global__ void __launch_bounds__(256) k_reduce(const float* __restrict__ W1,
                                                const float* __restrict__ b1,
                                                const float* __restrict__ g1,
                                                const float* __restrict__ be1,
                                                const float* __restrict__ m1,
                                                const float* __restrict__ v1) {
    __shared__ float2 W1p[2][DIN*32];           // packed (j, j+32) / (j+64, j+96)
    __shared__ float  sAcc[8][4][32];
    int tid = threadIdx.x, lane = tid & 31, w = tid >> 5;
    int t = blockIdx.y;

    for (int ii = tid; ii < 2*DIN*32; ii += 256) {
        int p = ii >> 11, rem = ii & 2047;
        int k = rem >> 5, l = rem & 31;
        W1p[p][k*32 + l] = make_float2(W1[k*H_ + p*64 + l],
                                       W1[k*H_ + p*64 + l + 32]);
    }
    float sc[4], sh[4];
#pragma unroll
    for (int q = 0; q < 4; q++) {
        int j = lane + 32*q;
        float s = g1[j] * rsqrtf(v1[j] + EPSB);
        sc[q] = s;
        sh[q] = (b1[j] - m1[j]) * s + be1[j];   // fold bias + BN shift
    }
    __syncthreads();

    const unsigned long long* Wp0 = (const unsigned long long*)W1p[0];
    const unsigned long long* Wp1 = (const unsigned long long*)W1p[1];
    float acc[4] = {0.f, 0.f, 0.f, 0.f};

    for (int i = blockIdx.x*8 + w; i < N_; i += gridDim.x*8) {
        int node = t*N_ + i;
        float2 xv = ((const float2*)g_xa4)[node*32 + lane];  // elems 2*lane, 2*lane+1
        float  wi = g_w2[node];
        unsigned long long a0 = 0ull, a1 = 0ull;
#pragma unroll
        for (int k = 0; k < DIN; k += 2) {
            float cA = __shfl_sync(0xffffffffu, xv.x, k >> 1);
            float cB = __shfl_sync(0xffffffffu, xv.y, k >> 1);
            unsigned long long c2 = pk2(cA, cA);
            a0 = ffma2(c2, Wp0[k*32 + lane], a0);
            a1 = ffma2(c2, Wp1[k*32 + lane], a1);
            c2 = pk2(cB, cB);
            a0 = ffma2(c2, Wp0[(k+1)*32 + lane], a0);
            a1 = ffma2(c2, Wp1[(k+1)*32 + lane], a1);
        }
        float2 y01 = upk2(a0), y23 = upk2(a1);
        acc[0] += wi * fmaxf(y01.x*sc[0] + sh[0], 0.f);
        acc[1] += wi * fmaxf(y01.y*sc[1] + sh[1], 0.f);
        acc[2] += wi * fmaxf(y23.x*sc[2] + sh[2], 0.f);
        acc[3] += wi * fmaxf(y23.y*sc[3] + sh[3], 0.f);
    }
#pragma unroll
    for (int q = 0; q < 4; q++) sAcc[w][q][lane] = acc[q];
    __syncthreads();
    if (tid < 128) {
        int q = tid >> 5, l = tid & 31;
        float s = 0.f;
#pragma unroll
        for (int ww = 0; ww < 8; ww++) s += sAcc[ww][q][l];
        atomicAdd(&g_S[t*H_ + q*32 + l], s);
    }
}

// ---------- K7: LSTM weight transpose/pack (coalesced float4 layout) ----------
__global__ void k_prep(const float* __restrict__ Wih0, const float* __restrict__ Whh0,
                       const float* __restrict__ Wih1, const float* __restrict__ Whh1,
                       const float* __restrict__ bih0, const float* __restrict__ bhh0,
                       const float* __restrict__ bih1, const float* __restrict__ bhh1) {
    int i = blockIdx.x * 256 + threadIdx.x;
    if (i < 1024) {
        int L = i >> 9, r = i & 511;
        g_bsum[L][r] = L ? (bih1[r] + bhh1[r]) : (bih0[r] + bhh0[r]);
    }
    if (i >= 4*32*512) return;
    int m = i >> 14, rem = i & 16383;
    int k4 = rem >> 9, r = rem & 511;
    const float* W = (m == 0) ? Wih0 : (m == 1) ? Whh0 : (m == 2) ? Wih1 : Whh1;
    g_WT4[m][k4*512 + r] = ((const float4*)W)[r*32 + k4];
}

__device__ __forceinline__ float sigf(float x) { return 1.f / (1.f + expf(-x)); }

// ---------- K8: finalize = (S/N)@W2+b2 -> BN2 -> emb; 2-layer LSTM; classifier ----------
__global__ void __launch_bounds__(512) k_final(const float* __restrict__ W2,
                                               const float* __restrict__ b2,
                                               const float* __restrict__ g2,
                                               const float* __restrict__ be2,
                                               const float* __restrict__ m2,
                                               const float* __restrict__ v2,
                                               const float* __restrict__ Wc,
                                               const float* __restrict__ bc,
                                               float* __restrict__ out) {
    __shared__ float Ssm[T_*H_];
    __shared__ float emb[T_][H_];
    __shared__ float h0[H_], c0[H_], h1[H_], c1[H_];
    __shared__ float gates[512];
    int tid = threadIdx.x;

    for (int i = tid; i < T_*H_; i += 512) Ssm[i] = g_S[i] * (1.0f / N_);
    if (tid < H_) { h0[tid] = 0.f; c0[tid] = 0.f; h1[tid] = 0.f; c1[tid] = 0.f; }
    __syncthreads();

    for (int item = tid; item < T_*H_; item += 512) {
        int t = item >> 7, j = item & 127;
        float s2  = g2[j] * rsqrtf(v2[j] + EPSB);
        float sh2 = be2[j] - m2[j]*s2;
        float acc = b2[j];
#pragma unroll 8
        for (int k = 0; k < H_; k++) acc += Ssm[t*H_ + k] * W2[k*H_ + j];
        emb[t][j] = acc*s2 + sh2;
    }
    __syncthreads();

    int r = tid;
    for (int t = 0; t < T_; t++) {
        // layer 0
        float acc = g_bsum[0][r];
#pragma unroll 8
        for (int k4 = 0; k4 < 32; k4++) {
            float4 wx = g_WT4[0][k4*512 + r];
            float4 wh = g_WT4[1][k4*512 + r];
            int k = k4*4;
            acc += wx.x*emb[t][k] + wx.y*emb[t][k+1] + wx.z*emb[t][k+2] + wx.w*emb[t][k+3];
            acc += wh.x*h0[k]     + wh.y*h0[k+1]     + wh.z*h0[k+2]     + wh.w*h0[k+3];
        }
        gates[r] = acc;
        __syncthreads();
        if (tid < H_) {
            int j = tid;
            float ig = sigf(gates[j]);
            float fg = sigf(gates[H_ + j]);
            float gg = tanhf(gates[2*H_ + j]);
            float og = sigf(gates[3*H_ + j]);
            float cn = fg*c0[j] + ig*gg;
            c0[j] = cn;
            h0[j] = og * tanhf(cn);
        }
        __syncthreads();
        // layer 1 (input = h0)
        acc = g_bsum[1][r];
#pragma unroll 8
        for (int k4 = 0; k4 < 32; k4++) {
            float4 wx = g_WT4[2][k4*512 + r];
            float4 wh = g_WT4[3][k4*512 + r];
            int k = k4*4;
            acc += wx.x*h0[k] + wx.y*h0[k+1] + wx.z*h0[k+2] + wx.w*h0[k+3];
            acc += wh.x*h1[k] + wh.y*h1[k+1] + wh.z*h1[k+2] + wh.w*h1[k+3];
        }
        gates[r] = acc;
        __syncthreads();
        if (tid < H_) {
            int j = tid;
            float ig = sigf(gates[j]);
            float fg = sigf(gates[H_ + j]);
            float gg = tanhf(gates[2*H_ + j]);
            float og = sigf(gates[3*H_ + j]);
            float cn = fg*c1[j] + ig*gg;
            c1[j] = cn;
            h1[j] = og * tanhf(cn);
        }
        __syncthreads();
    }

    if (tid < 2) {
        float acc = bc[tid];
#pragma unroll 8
        for (int k = 0; k < H_; k++) acc += Wc[tid*H_ + k] * h1[k];
        out[tid] = acc;
    }
    if (tid < H_) out[2 + tid] = h1[tid];
}

// ---------- launch ----------
extern "C" void kernel_launch(void* const* d_in, const int* in_sizes, int n_in,
                              void* d_out, int out_size) {
    const float* x    = (const float*)d_in[0];
    const int*   ei   = (const int*)  d_in[1];
    const float* W1   = (const float*)d_in[2];
    const float* b1   = (const float*)d_in[3];
    const float* g1   = (const float*)d_in[4];
    const float* be1  = (const float*)d_in[5];
    const float* m1   = (const float*)d_in[6];
    const float* v1   = (const float*)d_in[7];
    const float* W2   = (const float*)d_in[8];
    const float* b2   = (const float*)d_in[9];
    const float* g2   = (const float*)d_in[10];
    const float* be2  = (const float*)d_in[11];
    const float* m2   = (const float*)d_in[12];
    const float* v2   = (const float*)d_in[13];
    const float* Wih0 = (const float*)d_in[14];
    const float* Whh0 = (const float*)d_in[15];
    const float* bih0 = (const float*)d_in[16];
    const float* bhh0 = (const float*)d_in[17];
    const float* Wih1 = (const float*)d_in[18];
    const float* Whh1 = (const float*)d_in[19];
    const float* bih1 = (const float*)d_in[20];
    const float* bhh1 = (const float*)d_in[21];
    const float* Wc   = (const float*)d_in[22];
    const float* bc   = (const float*)d_in[23];

    k_zero  <<<(T_*N_ + 255)/256, 256>>>();
    k_count <<<(T_*E_ + 255)/256, 256>>>(ei);
    k_dinv  <<<(T_*N_ + 255)/256, 256>>>();
    k_xainit<<<(T_*N_*16 + 255)/256, 256>>>(x);
    k_scatter<<<(T_*E_*4 + 255)/256, 256>>>(ei, x);
    k_reduce<<<dim3(74, T_), 256>>>(W1, b1, g1, be1, m1, v1);
    k_prep  <<<256, 256>>>(Wih0, Whh0, Wih1, Whh1, bih0, bhh0, bih1, bhh1);
    k_final <<<1, 512>>>(W2, b2, g2, be2, m2, v2, Wc, bc, (float*)d_out);
}

// round 2
// speedup vs baseline: 1.1625x; 1.1625x over previous
#include <cuda_runtime.h>
#include <math.h>

#define T_  8
#define N_  20000
#define E_  320000
#define DIN 64
#define H_  128
#define EPSB 1e-5f

#define SCAN_N (T_*N_)
#define SCAN_B 2048
#define NBLK ((SCAN_N + SCAN_B - 1)/SCAN_B)   // 79
#define TE (T_*E_)

// ---------- scratch (device globals: no allocation allowed) ----------
__device__ int    g_deg  [SCAN_N];
__device__ float  g_dinv [SCAN_N];
__device__ float  g_w2   [SCAN_N];
__device__ int    g_off  [SCAN_N + 1];
__device__ int    g_cursor[SCAN_N];
__device__ int    g_bsum [NBLK];
__device__ int    g_srcs [TE];
__device__ float  g_ecoef[TE];
__device__ float  g_S    [T_*H_];
__device__ float4 g_WT4  [4][32*512];
__device__ float  g_bsumL[2][512];

// ---------- f32x2 packed helpers ----------
__device__ __forceinline__ unsigned long long pk2(float a, float b) {
    unsigned long long r;
    asm("mov.b64 %0, {%1, %2};" : "=l"(r) : "f"(a), "f"(b));
    return r;
}
__device__ __forceinline__ unsigned long long ffma2(unsigned long long a,
                                                    unsigned long long b,
                                                    unsigned long long c) {
    unsigned long long d;
    asm("fma.rn.f32x2 %0, %1, %2, %3;" : "=l"(d) : "l"(a), "l"(b), "l"(c));
    return d;
}
__device__ __forceinline__ float2 upk2(unsigned long long v) {
    float2 f;
    asm("mov.b64 {%0, %1}, %2;" : "=f"(f.x), "=f"(f.y) : "l"(v));
    return f;
}

// ---------- K1: zero deg + S ----------
__global__ void k_zero() {
    int i = blockIdx.x * blockDim.x + threadIdx.x;
    if (i < SCAN_N) g_deg[i] = 0;
    if (i < T_*H_)  g_S[i]   = 0.f;
}

// ---------- K2: in-degree count (dst side) ----------
__global__ void k_count(const int* __restrict__ ei) {
    int i = blockIdx.x * blockDim.x + threadIdx.x;
    if (i >= TE) return;
    int t = i / E_, e = i - t*E_;
    int dst = ei[t*2*E_ + E_ + e];
    atomicAdd(&g_deg[t*N_ + dst], 1);
}

// ---------- K3: dinv + w2 self-loop term ----------
__global__ void k_dinv() {
    int i = blockIdx.x * blockDim.x + threadIdx.x;
    if (i >= SCAN_N) return;
    float d = rsqrtf(1.0f + (float)g_deg[i]);
    g_dinv[i] = d;
    g_w2[i]   = d * d;
}

// ---------- scan: exclusive prefix sum of deg -> CSR offsets ----------
__global__ void __launch_bounds__(512) k_scan1() {
    __shared__ int wsum[16];
    int tid = threadIdx.x, lane = tid & 31, w = tid >> 5;
    int base = blockIdx.x*SCAN_B + tid*4;
    int v[4]; int tot = 0;
#pragma unroll
    for (int u = 0; u < 4; u++) {
        v[u] = (base + u < SCAN_N) ? g_deg[base + u] : 0;
        tot += v[u];
    }
    int incl = tot;
#pragma unroll
    for (int d = 1; d < 32; d <<= 1) {
        int n = __shfl_up_sync(0xffffffffu, incl, d);
        if (lane >= d) incl += n;
    }
    int excl = incl - tot;
    if (lane == 31) wsum[w] = incl;
    __syncthreads();
    if (w == 0) {
        int s = (lane < 16) ? wsum[lane] : 0;
        int inc = s;
#pragma unroll
        for (int d = 1; d < 32; d <<= 1) {
            int n = __shfl_up_sync(0xffffffffu, inc, d);
            if (lane >= d) inc += n;
        }
        if (lane < 16) wsum[lane] = inc - s;
    }
    __syncthreads();
    int run = excl + wsum[w];
#pragma unroll
    for (int u = 0; u < 4; u++) {
        if (base + u < SCAN_N) g_off[base + u] = run;
        run += v[u];
    }
    if (tid == 511) g_bsum[blockIdx.x] = run;
}

__global__ void k_scan2() {
    __shared__ int s[NBLK];
    int tid = threadIdx.x;
    if (tid < NBLK) s[tid] = g_bsum[tid];
    __syncthreads();
    if (tid == 0) {
        int r = 0;
        for (int i = 0; i < NBLK; i++) { int v = s[i]; s[i] = r; r += v; }
    }
    __syncthreads();
    if (tid < NBLK) g_bsum[tid] = s[tid];
}

__global__ void k_scan3() {
    int i = blockIdx.x*blockDim.x + threadIdx.x;
    if (i < SCAN_N) {
        int o = g_off[i] + g_bsum[i / SCAN_B];
        g_off[i] = o;
        g_cursor[i] = o;
    }
    if (i == 0) g_off[SCAN_N] = TE;
}

// ---------- K5: fill CSR (src + coef per edge) + w2 scalar scatter ----------
__global__ void __launch_bounds__(256) k_fill(const int* __restrict__ ei) {
    int i = blockIdx.x*256 + threadIdx.x;
    if (i >= TE) return;
    int t = i / E_, e = i - t*E_;
    int src = ei[t*2*E_ + e];
    int dst = ei[t*2*E_ + E_ + e];
    int ns = t*N_ + src, nd = t*N_ + dst;
    float c = g_dinv[ns] * g_dinv[nd];
    atomicAdd(&g_w2[ns], c);
    int pos = atomicAdd(&g_cursor[nd], 1);
    g_srcs[pos]  = src;
    g_ecoef[pos] = c;
}

// ---------- K6: fused CSR gather -> (agg @ W1 + b1) -> BN1 -> ReLU -> weighted sum ----------
__global__ void __launch_bounds__(256) k_gnn(const float* __restrict__ x,
                                             const float* __restrict__ W1,
                                             const float* __restrict__ b1,
                                             const float* __restrict__ g1,
                                             const float* __restrict__ be1,
                                             const float* __restrict__ m1,
                                             const float* __restrict__ v1) {
    __shared__ float2 W1p[2][DIN*32];
    __shared__ float  sAcc[8][4][32];
    int tid = threadIdx.x, lane = tid & 31, w = tid >> 5;
    int t = blockIdx.y;

    for (int ii = tid; ii < 2*DIN*32; ii += 256) {
        int p = ii >> 11, rem = ii & 2047;
        int k = rem >> 5, l = rem & 31;
        W1p[p][k*32 + l] = make_float2(W1[k*H_ + p*64 + l],
                                       W1[k*H_ + p*64 + l + 32]);
    }
    float sc[4], sh[4];
#pragma unroll
    for (int q = 0; q < 4; q++) {
        int j = lane + 32*q;
        float s = g1[j] * rsqrtf(v1[j] + EPSB);
        sc[q] = s;
        sh[q] = (b1[j] - m1[j]) * s + be1[j];
    }
    __syncthreads();

    const float2* x2 = (const float2*)x;
    const unsigned long long* Wp0 = (const unsigned long long*)W1p[0];
    const unsigned long long* Wp1 = (const unsigned long long*)W1p[1];
    float acc[4] = {0.f, 0.f, 0.f, 0.f};

    for (int i = blockIdx.x*8 + w; i < N_; i += gridDim.x*8) {
        int node = t*N_ + i;
        float dself = g_dinv[node];
        float2 xv = x2[(size_t)node*32 + lane];
        float2 a;
        a.x = dself*dself*xv.x;
        a.y = dself*dself*xv.y;

        int o0 = g_off[node], o1 = g_off[node + 1];
        for (int j = o0; j < o1; j += 32) {
            int cnt = min(32, o1 - j);
            int   s = 0;
            float c = 0.f;
            if (lane < cnt) { s = g_srcs[j + lane]; c = g_ecoef[j + lane]; }
            for (int jj = 0; jj < cnt; jj++) {
                int   ss = __shfl_sync(0xffffffffu, s, jj);
                float cc = __shfl_sync(0xffffffffu, c, jj);
                float2 xs = x2[((size_t)(t*N_ + ss))*32 + lane];
                a.x = fmaf(cc, xs.x, a.x);
                a.y = fmaf(cc, xs.y, a.y);
            }
        }

        // matmul 64 -> 128 via f32x2
        unsigned long long a0 = 0ull, a1 = 0ull;
#pragma unroll
        for (int k = 0; k < DIN; k += 2) {
            float cA = __shfl_sync(0xffffffffu, a.x, k >> 1);
            float cB = __shfl_sync(0xffffffffu, a.y, k >> 1);
            unsigned long long c2 = pk2(cA, cA);
            a0 = ffma2(c2, Wp0[k*32 + lane], a0);
            a1 = ffma2(c2, Wp1[k*32 + lane], a1);
            c2 = pk2(cB, cB);
            a0 = ffma2(c2, Wp0[(k+1)*32 + lane], a0);
            a1 = ffma2(c2, Wp1[(k+1)*32 + lane], a1);
        }
        float2 y01 = upk2(a0), y23 = upk2(a1);
        float wi = g_w2[node];
        acc[0] += wi * fmaxf(y01.x*sc[0] + sh[0], 0.f);
        acc[1] += wi * fmaxf(y01.y*sc[1] + sh[1], 0.f);
        acc[2] += wi * fmaxf(y23.x*sc[2] + sh[2], 0.f);
        acc[3] += wi * fmaxf(y23.y*sc[3] + sh[3], 0.f);
    }
#pragma unroll
    for (int q = 0; q < 4; q++) sAcc[w][q][lane] = acc[q];
    __syncthreads();
    if (tid < 128) {
        int q = tid >> 5, l = tid & 31;
        float s = 0.f;
#pragma unroll
        for (int ww = 0; ww < 8; ww++) s += sAcc[ww][q][l];
        atomicAdd(&g_S[t*H_ + q*32 + l], s);
    }
}

// ---------- K7: LSTM weight transpose/pack ----------
__global__ void k_prep(const float* __restrict__ Wih0, const float* __restrict__ Whh0,
                       const float* __restrict__ Wih1, const float* __restrict__ Whh1,
                       const float* __restrict__ bih0, const float* __restrict__ bhh0,
                       const float* __restrict__ bih1, const float* __restrict__ bhh1) {
    int i = blockIdx.x * 256 + threadIdx.x;
    if (i < 1024) {
        int L = i >> 9, r = i & 511;
        g_bsumL[L][r] = L ? (bih1[r] + bhh1[r]) : (bih0[r] + bhh0[r]);
    }
    if (i >= 4*32*512) return;
    int m = i >> 14, rem = i & 16383;
    int k4 = rem >> 9, r = rem & 511;
    const float* W = (m == 0) ? Wih0 : (m == 1) ? Whh0 : (m == 2) ? Wih1 : Whh1;
    g_WT4[m][k4*512 + r] = ((const float4*)W)[r*32 + k4];
}

__device__ __forceinline__ float sigf(float x) { return 1.f / (1.f + expf(-x)); }

// ---------- K8: finalize ----------
__global__ void __launch_bounds__(512) k_final(const float* __restrict__ W2,
                                               const float* __restrict__ b2,
                                               const float* __restrict__ g2,
                                               const float* __restrict__ be2,
                                               const float* __restrict__ m2,
                                               const float* __restrict__ v2,
                                               const float* __restrict__ Wc,
                                               const float* __restrict__ bc,
                                               float* __restrict__ out) {
    __shared__ float Ssm[T_*H_];
    __shared__ float emb[T_][H_];
    __shared__ float h0[H_], c0[H_], h1[H_], c1[H_];
    __shared__ float gates[512];
    int tid = threadIdx.x;

    for (int i = tid; i < T_*H_; i += 512) Ssm[i] = g_S[i] * (1.0f / N_);
    if (tid < H_) { h0[tid] = 0.f; c0[tid] = 0.f; h1[tid] = 0.f; c1[tid] = 0.f; }
    __syncthreads();

    for (int item = tid; item < T_*H_; item += 512) {
        int t = item >> 7, j = item & 127;
        float s2  = g2[j] * rsqrtf(v2[j] + EPSB);
        float sh2 = be2[j] - m2[j]*s2;
        float acc = b2[j];
#pragma unroll 8
        for (int k = 0; k < H_; k++) acc += Ssm[t*H_ + k] * W2[k*H_ + j];
        emb[t][j] = acc*s2 + sh2;
    }
    __syncthreads();

    int r = tid;
    for (int t = 0; t < T_; t++) {
        float acc = g_bsumL[0][r];
#pragma unroll 8
        for (int k4 = 0; k4 < 32; k4++) {
            float4 wx = g_WT4[0][k4*512 + r];
            float4 wh = g_WT4[1][k4*512 + r];
            int k = k4*4;
            acc += wx.x*emb[t][k] + wx.y*emb[t][k+1] + wx.z*emb[t][k+2] + wx.w*emb[t][k+3];
            acc += wh.x*h0[k]     + wh.y*h0[k+1]     + wh.z*h0[k+2]     + wh.w*h0[k+3];
        }
        gates[r] = acc;
        __syncthreads();
        if (tid < H_) {
            int j = tid;
            float ig = sigf(gates[j]);
            float fg = sigf(gates[H_ + j]);
            float gg = tanhf(gates[2*H_ + j]);
            float og = sigf(gates[3*H_ + j]);
            float cn = fg*c0[j] + ig*gg;
            c0[j] = cn;
            h0[j] = og * tanhf(cn);
        }
        __syncthreads();
        acc = g_bsumL[1][r];
#pragma unroll 8
        for (int k4 = 0; k4 < 32; k4++) {
            float4 wx = g_WT4[2][k4*512 + r];
            float4 wh = g_WT4[3][k4*512 + r];
            int k = k4*4;
            acc += wx.x*h0[k] + wx.y*h0[k+1] + wx.z*h0[k+2] + wx.w*h0[k+3];
            acc += wh.x*h1[k] + wh.y*h1[k+1] + wh.z*h1[k+2] + wh.w*h1[k+3];
        }
        gates[r] = acc;
        __syncthreads();
        if (tid < H_) {
            int j = tid;
            float ig = sigf(gates[j]);
            float fg = sigf(gates[H_ + j]);
            float gg = tanhf(gates[2*H_ + j]);
            float og = sigf(gates[3*H_ + j]);
            float cn = fg*c1[j] + ig*gg;
            c1[j] = cn;
            h1[j] = og * tanhf(cn);
        }
        __syncthreads();
    }

    if (tid < 2) {
        float acc = bc[tid];
#pragma unroll 8
        for (int k = 0; k < H_; k++) acc += Wc[tid*H_ + k] * h1[k];
        out[tid] = acc;
    }
    if (tid < H_) out[2 + tid] = h1[tid];
}

// ---------- launch ----------
extern "C" void kernel_launch(void* const* d_in, const int* in_sizes, int n_in,
                              void* d_out, int out_size) {
    const float* x    = (const float*)d_in[0];
    const int*   ei   = (const int*)  d_in[1];
    const float* W1   = (const float*)d_in[2];
    const float* b1   = (const float*)d_in[3];
    const float* g1   = (const float*)d_in[4];
    const float* be1  = (const float*)d_in[5];
    const float* m1   = (const float*)d_in[6];
    const float* v1   = (const float*)d_in[7];
    const float* W2   = (const float*)d_in[8];
    const float* b2   = (const float*)d_in[9];
    const float* g2   = (const float*)d_in[10];
    const float* be2  = (const float*)d_in[11];
    const float* m2   = (const float*)d_in[12];
    const float* v2   = (const float*)d_in[13];
    const float* Wih0 = (const float*)d_in[14];
    const float* Whh0 = (const float*)d_in[15];
    const float* bih0 = (const float*)d_in[16];
    const float* bhh0 = (const float*)d_in[17];
    const float* Wih1 = (const float*)d_in[18];
    const float* Whh1 = (const float*)d_in[19];
    const float* bih1 = (const float*)d_in[20];
    const float* bhh1 = (const float*)d_in[21];
    const float* Wc   = (const float*)d_in[22];
    const float* bc   = (const float*)d_in[23];

    k_zero <<<(SCAN_N + 255)/256, 256>>>();
    k_count<<<(TE + 255)/256, 256>>>(ei);
    k_dinv <<<(SCAN_N + 255)/256, 256>>>();
    k_scan1<<<NBLK, 512>>>();
    k_scan2<<<1, 128>>>();
    k_scan3<<<(SCAN_N + 255)/256, 256>>>();
    k_fill <<<(TE + 255)/256, 256>>>(ei);
    k_gnn  <<<dim3(74, T_), 256>>>(x, W1, b1, g1, be1, m1, v1);
    k_prep <<<256, 256>>>(Wih0, Whh0, Wih1, Whh1, bih0, bhh0, bih1, bhh1);
    k_final<<<1, 512>>>(W2, b2, g2, be2, m2, v2, Wc, bc, (float*)d_out);
}

// round 3
// speedup vs baseline: 1.2018x; 1.0338x over previous
#include <cuda_runtime.h>
#include <math.h>

#define T_  8
#define N_  20000
#define E_  320000
#define DIN 64
#define H_  128
#define EPSB 1e-5f

#define SCAN_N (T_*N_)
#define SCAN_B 2048
#define NBLK ((SCAN_N + SCAN_B - 1)/SCAN_B)   // 79
#define TE (T_*E_)

// ---------- scratch (device globals: no allocation allowed) ----------
__device__ int    g_deg  [SCAN_N];
__device__ float  g_dinv [SCAN_N];
__device__ float  g_w2   [SCAN_N];
__device__ int    g_off  [SCAN_N + 1];
__device__ int    g_cursor[SCAN_N];
__device__ int    g_bsum [NBLK];
__device__ int    g_srcs [TE];
__device__ float4 g_y4   [SCAN_N*16];        // dinv-scaled x rows, [node][64] as float4
__device__ float  g_S    [T_*H_];
__device__ float4 g_WT4  [4][32*512];
__device__ float  g_bsumL[2][512];

// ---------- f32x2 packed helpers ----------
__device__ __forceinline__ unsigned long long pk2(float a, float b) {
    unsigned long long r;
    asm("mov.b64 %0, {%1, %2};" : "=l"(r) : "f"(a), "f"(b));
    return r;
}
__device__ __forceinline__ unsigned long long ffma2(unsigned long long a,
                                                    unsigned long long b,
                                                    unsigned long long c) {
    unsigned long long d;
    asm("fma.rn.f32x2 %0, %1, %2, %3;" : "=l"(d) : "l"(a), "l"(b), "l"(c));
    return d;
}
__device__ __forceinline__ float2 upk2(unsigned long long v) {
    float2 f;
    asm("mov.b64 {%0, %1}, %2;" : "=f"(f.x), "=f"(f.y) : "l"(v));
    return f;
}

// ---------- K1: zero deg/S + LSTM weight transpose (fused, independent work) ----------
__global__ void k_zeroprep(const float* __restrict__ Wih0, const float* __restrict__ Whh0,
                           const float* __restrict__ Wih1, const float* __restrict__ Whh1,
                           const float* __restrict__ bih0, const float* __restrict__ bhh0,
                           const float* __restrict__ bih1, const float* __restrict__ bhh1) {
    int i = blockIdx.x * 256 + threadIdx.x;
    if (i < SCAN_N) g_deg[i] = 0;
    if (i < T_*H_)  g_S[i]   = 0.f;
    if (i < 1024) {
        int L = i >> 9, r = i & 511;
        g_bsumL[L][r] = L ? (bih1[r] + bhh1[r]) : (bih0[r] + bhh0[r]);
    }
    if (i < 4*32*512) {
        int m = i >> 14, rem = i & 16383;
        int k4 = rem >> 9, r = rem & 511;
        const float* W = (m == 0) ? Wih0 : (m == 1) ? Whh0 : (m == 2) ? Wih1 : Whh1;
        g_WT4[m][k4*512 + r] = ((const float4*)W)[r*32 + k4];
    }
}

// ---------- K2: in-degree count (dst side) ----------
__global__ void k_count(const int* __restrict__ ei) {
    int i = blockIdx.x * blockDim.x + threadIdx.x;
    if (i >= TE) return;
    int t = i / E_, e = i - t*E_;
    int dst = ei[t*2*E_ + E_ + e];
    atomicAdd(&g_deg[t*N_ + dst], 1);
}

// ---------- K3: dinv + w2 self term + scaled rows y = dinv * x ----------
__global__ void __launch_bounds__(256) k_dinvscale(const float* __restrict__ x) {
    int i = blockIdx.x * 256 + threadIdx.x;
    if (i >= SCAN_N*16) return;
    int node = i >> 4;
    float d = rsqrtf(1.0f + (float)g_deg[node]);
    float4 v = ((const float4*)x)[i];
    g_y4[i] = make_float4(d*v.x, d*v.y, d*v.z, d*v.w);
    if ((i & 15) == 0) {
        g_dinv[node] = d;
        g_w2[node]   = d * d;
    }
}

// ---------- scan: exclusive prefix sum of deg -> CSR offsets ----------
__global__ void __launch_bounds__(512) k_scan1() {
    __shared__ int wsum[16];
    int tid = threadIdx.x, lane = tid & 31, w = tid >> 5;
    int base = blockIdx.x*SCAN_B + tid*4;
    int v[4]; int tot = 0;
#pragma unroll
    for (int u = 0; u < 4; u++) {
        v[u] = (base + u < SCAN_N) ? g_deg[base + u] : 0;
        tot += v[u];
    }
    int incl = tot;
#pragma unroll
    for (int d = 1; d < 32; d <<= 1) {
        int n = __shfl_up_sync(0xffffffffu, incl, d);
        if (lane >= d) incl += n;
    }
    int excl = incl - tot;
    if (lane == 31) wsum[w] = incl;
    __syncthreads();
    if (w == 0) {
        int s = (lane < 16) ? wsum[lane] : 0;
        int inc = s;
#pragma unroll
        for (int d = 1; d < 32; d <<= 1) {
            int n = __shfl_up_sync(0xffffffffu, inc, d);
            if (lane >= d) inc += n;
        }
        if (lane < 16) wsum[lane] = inc - s;
    }
    __syncthreads();
    int run = excl + wsum[w];
#pragma unroll
    for (int u = 0; u < 4; u++) {
        if (base + u < SCAN_N) g_off[base + u] = run;
        run += v[u];
    }
    if (tid == 511) g_bsum[blockIdx.x] = run;
}

__global__ void k_scan2() {
    __shared__ int s[NBLK];
    int tid = threadIdx.x;
    if (tid < NBLK) s[tid] = g_bsum[tid];
    __syncthreads();
    if (tid == 0) {
        int r = 0;
        for (int i = 0; i < NBLK; i++) { int v = s[i]; s[i] = r; r += v; }
    }
    __syncthreads();
    if (tid < NBLK) g_bsum[tid] = s[tid];
}

__global__ void k_scan3() {
    int i = blockIdx.x*blockDim.x + threadIdx.x;
    if (i < SCAN_N) {
        int o = g_off[i] + g_bsum[i / SCAN_B];
        g_off[i] = o;
        g_cursor[i] = o;
    }
    if (i == 0) g_off[SCAN_N] = TE;
}

// ---------- K5: fill CSR (src only) + w2 scalar scatter ----------
__global__ void __launch_bounds__(256) k_fill(const int* __restrict__ ei) {
    int i = blockIdx.x*256 + threadIdx.x;
    if (i >= TE) return;
    int t = i / E_, e = i - t*E_;
    int src = ei[t*2*E_ + e];
    int dst = ei[t*2*E_ + E_ + e];
    int ns = t*N_ + src, nd = t*N_ + dst;
    float c = g_dinv[ns] * g_dinv[nd];
    atomicAdd(&g_w2[ns], c);
    int pos = atomicAdd(&g_cursor[nd], 1);
    g_srcs[pos] = src;
}

// ---------- K6: fused gather (4 edges/warp in parallel) -> W1 -> BN1 -> ReLU -> weighted sum ----------
__global__ void __launch_bounds__(256) k_gnn(const float* __restrict__ W1,
                                             const float* __restrict__ b1,
                                             const float* __restrict__ g1,
                                             const float* __restrict__ be1,
                                             const float* __restrict__ m1,
                                             const float* __restrict__ v1) {
    __shared__ float2 W1p[2][DIN*32];
    __shared__ float  sAcc[8][4][32];
    int tid = threadIdx.x, lane = tid & 31, w = tid >> 5;
    int grp = lane >> 3, l = lane & 7;
    int t = blockIdx.y;

    for (int ii = tid; ii < 2*DIN*32; ii += 256) {
        int p = ii >> 11, rem = ii & 2047;
        int k = rem >> 5, ll = rem & 31;
        W1p[p][k*32 + ll] = make_float2(W1[k*H_ + p*64 + ll],
                                        W1[k*H_ + p*64 + ll + 32]);
    }
    float sc[4], sh[4];
#pragma unroll
    for (int q = 0; q < 4; q++) {
        int j = lane + 32*q;
        float s = g1[j] * rsqrtf(v1[j] + EPSB);
        sc[q] = s;
        sh[q] = (b1[j] - m1[j]) * s + be1[j];
    }
    __syncthreads();

    const unsigned long long* Wp0 = (const unsigned long long*)W1p[0];
    const unsigned long long* Wp1 = (const unsigned long long*)W1p[1];
    const float4* ybase = g_y4 + (size_t)(t*N_)*16;
    float acc[4] = {0.f, 0.f, 0.f, 0.f};

    for (int i = blockIdx.x*8 + w; i < N_; i += gridDim.x*8) {
        int node = t*N_ + i;
        // self term (group 0 only; others start at zero)
        float4 a0, a1;
        if (grp == 0) {
            a0 = ybase[(size_t)i*16 + l];
            a1 = ybase[(size_t)i*16 + l + 8];
        } else {
            a0 = make_float4(0.f, 0.f, 0.f, 0.f);
            a1 = make_float4(0.f, 0.f, 0.f, 0.f);
        }
        int o0 = g_off[node], o1 = g_off[node + 1];
        for (int j = o0 + grp; j < o1; j += 4) {
            int s = g_srcs[j];
            const float4* ys = ybase + (size_t)s*16;
            float4 v0 = ys[l], v1 = ys[l + 8];
            a0.x += v0.x; a0.y += v0.y; a0.z += v0.z; a0.w += v0.w;
            a1.x += v1.x; a1.y += v1.y; a1.z += v1.z; a1.w += v1.w;
        }
        // combine the 4 groups (xor over lane bits 3,4)
#pragma unroll
        for (int m = 8; m <= 16; m <<= 1) {
            a0.x += __shfl_xor_sync(0xffffffffu, a0.x, m);
            a0.y += __shfl_xor_sync(0xffffffffu, a0.y, m);
            a0.z += __shfl_xor_sync(0xffffffffu, a0.z, m);
            a0.w += __shfl_xor_sync(0xffffffffu, a0.w, m);
            a1.x += __shfl_xor_sync(0xffffffffu, a1.x, m);
            a1.y += __shfl_xor_sync(0xffffffffu, a1.y, m);
            a1.z += __shfl_xor_sync(0xffffffffu, a1.z, m);
            a1.w += __shfl_xor_sync(0xffffffffu, a1.w, m);
        }
        float ds = g_dinv[node];
        a0.x *= ds; a0.y *= ds; a0.z *= ds; a0.w *= ds;
        a1.x *= ds; a1.y *= ds; a1.z *= ds; a1.w *= ds;

        // matmul 64 -> 128 via f32x2; lane c (0..7) holds chunk c (a0) and c+8 (a1)
        unsigned long long p0 = 0ull, p1 = 0ull;
#pragma unroll
        for (int c = 0; c < 16; c++) {
            float bx = __shfl_sync(0xffffffffu, (c < 8) ? a0.x : a1.x, c & 7);
            float by = __shfl_sync(0xffffffffu, (c < 8) ? a0.y : a1.y, c & 7);
            float bz = __shfl_sync(0xffffffffu, (c < 8) ? a0.z : a1.z, c & 7);
            float bw = __shfl_sync(0xffffffffu, (c < 8) ? a0.w : a1.w, c & 7);
            int k = c*4;
            unsigned long long c2;
            c2 = pk2(bx, bx); p0 = ffma2(c2, Wp0[(k+0)*32 + lane], p0);
                              p1 = ffma2(c2, Wp1[(k+0)*32 + lane], p1);
            c2 = pk2(by, by); p0 = ffma2(c2, Wp0[(k+1)*32 + lane], p0);
                              p1 = ffma2(c2, Wp1[(k+1)*32 + lane], p1);
            c2 = pk2(bz, bz); p0 = ffma2(c2, Wp0[(k+2)*32 + lane], p0);
                              p1 = ffma2(c2, Wp1[(k+2)*32 + lane], p1);
            c2 = pk2(bw, bw); p0 = ffma2(c2, Wp0[(k+3)*32 + lane], p0);
                              p1 = ffma2(c2, Wp1[(k+3)*32 + lane], p1);
        }
        float2 y01 = upk2(p0), y23 = upk2(p1);
        float wi = g_w2[node];
        acc[0] += wi * fmaxf(y01.x*sc[0] + sh[0], 0.f);
        acc[1] += wi * fmaxf(y01.y*sc[1] + sh[1], 0.f);
        acc[2] += wi * fmaxf(y23.x*sc[2] + sh[2], 0.f);
        acc[3] += wi * fmaxf(y23.y*sc[3] + sh[3], 0.f);
    }
#pragma unroll
    for (int q = 0; q < 4; q++) sAcc[w][q][lane] = acc[q];
    __syncthreads();
    if (tid < 128) {
        int q = tid >> 5, ll = tid & 31;
        float s = 0.f;
#pragma unroll
        for (int ww = 0; ww < 8; ww++) s += sAcc[ww][q][ll];
        atomicAdd(&g_S[t*H_ + q*32 + ll], s);
    }
}

__device__ __forceinline__ float sigf(float x) { return 1.f / (1.f + expf(-x)); }

// ---------- K8: finalize = (S/N)@W2+b2 -> BN2 -> emb; 2-layer LSTM; classifier ----------
__global__ void __launch_bounds__(512) k_final(const float* __restrict__ W2,
                                               const float* __restrict__ b2,
                                               const float* __restrict__ g2,
                                               const float* __restrict__ be2,
                                               const float* __restrict__ m2,
                                               const float* __restrict__ v2,
                                               const float* __restrict__ Wc,
                                               const float* __restrict__ bc,
                                               float* __restrict__ out) {
    __shared__ float Ssm[T_*H_];
    __shared__ float emb[T_][H_];
    __shared__ float h0[H_], c0[H_], h1[H_], c1[H_];
    __shared__ float gates[512];
    int tid = threadIdx.x;

    for (int i = tid; i < T_*H_; i += 512) Ssm[i] = g_S[i] * (1.0f / N_);
    if (tid < H_) { h0[tid] = 0.f; c0[tid] = 0.f; h1[tid] = 0.f; c1[tid] = 0.f; }
    __syncthreads();

    for (int item = tid; item < T_*H_; item += 512) {
        int t = item >> 7, j = item & 127;
        float s2  = g2[j] * rsqrtf(v2[j] + EPSB);
        float sh2 = be2[j] - m2[j]*s2;
        float acc = b2[j];
#pragma unroll 8
        for (int k = 0; k < H_; k++) acc += Ssm[t*H_ + k] * W2[k*H_ + j];
        emb[t][j] = acc*s2 + sh2;
    }
    __syncthreads();

    int r = tid;
    for (int t = 0; t < T_; t++) {
        float acc = g_bsumL[0][r];
#pragma unroll 8
        for (int k4 = 0; k4 < 32; k4++) {
            float4 wx = g_WT4[0][k4*512 + r];
            float4 wh = g_WT4[1][k4*512 + r];
            int k = k4*4;
            acc += wx.x*emb[t][k] + wx.y*emb[t][k+1] + wx.z*emb[t][k+2] + wx.w*emb[t][k+3];
            acc += wh.x*h0[k]     + wh.y*h0[k+1]     + wh.z*h0[k+2]     + wh.w*h0[k+3];
        }
        gates[r] = acc;
        __syncthreads();
        if (tid < H_) {
            int j = tid;
            float ig = sigf(gates[j]);
            float fg = sigf(gates[H_ + j]);
            float gg = tanhf(gates[2*H_ + j]);
            float og = sigf(gates[3*H_ + j]);
            float cn = fg*c0[j] + ig*gg;
            c0[j] = cn;
            h0[j] = og * tanhf(cn);
        }
        __syncthreads();
        acc = g_bsumL[1][r];
#pragma unroll 8
        for (int k4 = 0; k4 < 32; k4++) {
            float4 wx = g_WT4[2][k4*512 + r];
            float4 wh = g_WT4[3][k4*512 + r];
            int k = k4*4;
            acc += wx.x*h0[k] + wx.y*h0[k+1] + wx.z*h0[k+2] + wx.w*h0[k+3];
            acc += wh.x*h1[k] + wh.y*h1[k+1] + wh.z*h1[k+2] + wh.w*h1[k+3];
        }
        gates[r] = acc;
        __syncthreads();
        if (tid < H_) {
            int j = tid;
            float ig = sigf(gates[j]);
            float fg = sigf(gates[H_ + j]);
            float gg = tanhf(gates[2*H_ + j]);
            float og = sigf(gates[3*H_ + j]);
            float cn = fg*c1[j] + ig*gg;
            c1[j] = cn;
            h1[j] = og * tanhf(cn);
        }
        __syncthreads();
    }

    if (tid < 2) {
        float acc = bc[tid];
#pragma unroll 8
        for (int k = 0; k < H_; k++) acc += Wc[tid*H_ + k] * h1[k];
        out[tid] = acc;
    }
    if (tid < H_) out[2 + tid] = h1[tid];
}

// ---------- launch ----------
extern "C" void kernel_launch(void* const* d_in, const int* in_sizes, int n_in,
                              void* d_out, int out_size) {
    const float* x    = (const float*)d_in[0];
    const int*   ei   = (const int*)  d_in[1];
    const float* W1   = (const float*)d_in[2];
    const float* b1   = (const float*)d_in[3];
    const float* g1   = (const float*)d_in[4];
    const float* be1  = (const float*)d_in[5];
    const float* m1   = (const float*)d_in[6];
    const float* v1   = (const float*)d_in[7];
    const float* W2   = (const float*)d_in[8];
    const float* b2   = (const float*)d_in[9];
    const float* g2   = (const float*)d_in[10];
    const float* be2  = (const float*)d_in[11];
    const float* m2   = (const float*)d_in[12];
    const float* v2   = (const float*)d_in[13];
    const float* Wih0 = (const float*)d_in[14];
    const float* Whh0 = (const float*)d_in[15];
    const float* bih0 = (const float*)d_in[16];
    const float* bhh0 = (const float*)d_in[17];
    const float* Wih1 = (const float*)d_in[18];
    const float* Whh1 = (const float*)d_in[19];
    const float* bih1 = (const float*)d_in[20];
    const float* bhh1 = (const float*)d_in[21];
    const float* Wc   = (const float*)d_in[22];
    const float* bc   = (const float*)d_in[23];

    k_zeroprep <<<(SCAN_N + 255)/256, 256>>>(Wih0, Whh0, Wih1, Whh1,
                                             bih0, bhh0, bih1, bhh1);
    k_count    <<<(TE + 255)/256, 256>>>(ei);
    k_dinvscale<<<(SCAN_N*16 + 255)/256, 256>>>(x);
    k_scan1    <<<NBLK, 512>>>();
    k_scan2    <<<1, 128>>>();
    k_scan3    <<<(SCAN_N + 255)/256, 256>>>();
    k_fill     <<<(TE + 255)/256, 256>>>(ei);
    k_gnn      <<<dim3(74, T_), 256>>>(W1, b1, g1, be1, m1, v1);
    k_final    <<<1, 512>>>(W2, b2, g2, be2, m2, v2, Wc, bc, (float*)d_out);
}

// round 4
// speedup vs baseline: 1.2605x; 1.0489x over previous
#include <cuda_runtime.h>
#include <math.h>

#define T_  8
#define N_  20000
#define E_  320000
#define DIN 64
#define H_  128
#define EPSB 1e-5f

#define SCAN_N (T_*N_)
#define SCAN_B 2048
#define NBLK ((SCAN_N + SCAN_B - 1)/SCAN_B)   // 79 blocks (78.125 -> 79)
#define TE (T_*E_)

// ---------- scratch (device globals: no allocation allowed) ----------
__device__ int    g_deg  [SCAN_N];
__device__ float  g_dinv [SCAN_N];
__device__ float  g_w2   [SCAN_N];
__device__ int    g_off  [SCAN_N + 1];       // block-LOCAL exclusive offsets
__device__ int    g_cursor[SCAN_N];          // block-LOCAL cursors
__device__ int    g_bsum [NBLK];             // per-block edge sums (raw)
__device__ int    g_srcs [TE];
__device__ float4 g_y4   [SCAN_N*16];        // dinv-scaled x rows
__device__ float  g_S    [T_*H_];
__device__ float4 g_WT4  [4][32*512];
__device__ float  g_bsumL[2][512];

// ---------- f32x2 packed helpers ----------
__device__ __forceinline__ unsigned long long pk2(float a, float b) {
    unsigned long long r;
    asm("mov.b64 %0, {%1, %2};" : "=l"(r) : "f"(a), "f"(b));
    return r;
}
__device__ __forceinline__ unsigned long long ffma2(unsigned long long a,
                                                    unsigned long long b,
                                                    unsigned long long c) {
    unsigned long long d;
    asm("fma.rn.f32x2 %0, %1, %2, %3;" : "=l"(d) : "l"(a), "l"(b), "l"(c));
    return d;
}
__device__ __forceinline__ float2 upk2(unsigned long long v) {
    float2 f;
    asm("mov.b64 {%0, %1}, %2;" : "=f"(f.x), "=f"(f.y) : "l"(v));
    return f;
}

// ---------- in-block reconstruction of the 79-entry block prefix ----------
// sPre[b] = exclusive prefix over g_bsum[0..b)
__device__ __forceinline__ void block_prefix(int* sPre, int* sWp, int tid) {
    if (tid < 96) {
        int lane = tid & 31;
        int v = (tid < NBLK) ? g_bsum[tid] : 0;
        int incl = v;
#pragma unroll
        for (int d = 1; d < 32; d <<= 1) {
            int n = __shfl_up_sync(0xffffffffu, incl, d);
            if (lane >= d) incl += n;
        }
        if (lane == 31) sWp[tid >> 5] = incl;
        if (tid < NBLK) sPre[tid] = incl - v;
    }
    __syncthreads();
    if (tid < NBLK) {
        int w0 = tid >> 5;
        int c = 0;
        if (w0 > 0) c += sWp[0];
        if (w0 > 1) c += sWp[1];
        sPre[tid] += c;
    }
    __syncthreads();
}

// ---------- K1: zero deg/S + LSTM weight transpose ----------
__global__ void k_zeroprep(const float* __restrict__ Wih0, const float* __restrict__ Whh0,
                           const float* __restrict__ Wih1, const float* __restrict__ Whh1,
                           const float* __restrict__ bih0, const float* __restrict__ bhh0,
                           const float* __restrict__ bih1, const float* __restrict__ bhh1) {
    int i = blockIdx.x * 256 + threadIdx.x;
    if (i < SCAN_N) g_deg[i] = 0;
    if (i < T_*H_)  g_S[i]   = 0.f;
    if (i < 1024) {
        int L = i >> 9, r = i & 511;
        g_bsumL[L][r] = L ? (bih1[r] + bhh1[r]) : (bih0[r] + bhh0[r]);
    }
    if (i < 4*32*512) {
        int m = i >> 14, rem = i & 16383;
        int k4 = rem >> 9, r = rem & 511;
        const float* W = (m == 0) ? Wih0 : (m == 1) ? Whh0 : (m == 2) ? Wih1 : Whh1;
        g_WT4[m][k4*512 + r] = ((const float4*)W)[r*32 + k4];
    }
}

// ---------- K2: in-degree count, int4-vectorized (4 edges/thread) ----------
__global__ void k_count(const int* __restrict__ ei) {
    int i = blockIdx.x * blockDim.x + threadIdx.x;
    if (i >= TE/4) return;
    int t = i / (E_/4), e4 = i - t*(E_/4);
    int4 d4 = ((const int4*)(ei + t*2*E_ + E_))[e4];
    int base = t*N_;
    atomicAdd(&g_deg[base + d4.x], 1);
    atomicAdd(&g_deg[base + d4.y], 1);
    atomicAdd(&g_deg[base + d4.z], 1);
    atomicAdd(&g_deg[base + d4.w], 1);
}

// ---------- K3: block-local scan of deg + dinv/w2 ----------
__global__ void __launch_bounds__(512) k_scan1() {
    __shared__ int wsum[16];
    int tid = threadIdx.x, lane = tid & 31, w = tid >> 5;
    int base = blockIdx.x*SCAN_B + tid*4;
    int v[4]; int tot = 0;
#pragma unroll
    for (int u = 0; u < 4; u++) {
        v[u] = (base + u < SCAN_N) ? g_deg[base + u] : 0;
        tot += v[u];
    }
#pragma unroll
    for (int u = 0; u < 4; u++) {
        if (base + u < SCAN_N) {
            float d = rsqrtf(1.0f + (float)v[u]);
            g_dinv[base + u] = d;
            g_w2[base + u]   = d * d;
        }
    }
    int incl = tot;
#pragma unroll
    for (int d = 1; d < 32; d <<= 1) {
        int n = __shfl_up_sync(0xffffffffu, incl, d);
        if (lane >= d) incl += n;
    }
    int excl = incl - tot;
    if (lane == 31) wsum[w] = incl;
    __syncthreads();
    if (w == 0) {
        int s = (lane < 16) ? wsum[lane] : 0;
        int inc = s;
#pragma unroll
        for (int d = 1; d < 32; d <<= 1) {
            int n = __shfl_up_sync(0xffffffffu, inc, d);
            if (lane >= d) inc += n;
        }
        if (lane < 16) wsum[lane] = inc - s;
    }
    __syncthreads();
    int run = excl + wsum[w];
#pragma unroll
    for (int u = 0; u < 4; u++) {
        if (base + u <= SCAN_N) {           // includes sentinel at SCAN_N
            g_off[base + u] = run;
            if (base + u < SCAN_N) g_cursor[base + u] = run;
        }
        run += v[u];
    }
    if (tid == 511) g_bsum[blockIdx.x] = run;
}

// ---------- K4 (PROFILED SLOT): fill CSR + w2 scalar scatter, int4-vectorized ----------
__global__ void __launch_bounds__(256) k_fill(const int* __restrict__ ei) {
    __shared__ int sPre[NBLK];
    __shared__ int sWp[3];
    int tid = threadIdx.x;
    block_prefix(sPre, sWp, tid);

    int i = blockIdx.x*256 + tid;
    if (i >= TE/4) return;
    int t = i / (E_/4), e4 = i - t*(E_/4);
    int4 s4 = ((const int4*)(ei + t*2*E_))[e4];
    int4 d4 = ((const int4*)(ei + t*2*E_ + E_))[e4];
    int base = t*N_;
#pragma unroll
    for (int u = 0; u < 4; u++) {
        int src = (u == 0) ? s4.x : (u == 1) ? s4.y : (u == 2) ? s4.z : s4.w;
        int dst = (u == 0) ? d4.x : (u == 1) ? d4.y : (u == 2) ? d4.z : d4.w;
        int ns = base + src, nd = base + dst;
        float c = g_dinv[ns] * g_dinv[nd];
        atomicAdd(&g_w2[ns], c);
        int pos = atomicAdd(&g_cursor[nd], 1) + sPre[nd >> 11];
        g_srcs[pos] = src;
    }
}

// ---------- K5: scaled rows y = dinv * x ----------
__global__ void __launch_bounds__(256) k_yscale(const float* __restrict__ x) {
    int i = blockIdx.x * 256 + threadIdx.x;
    if (i >= SCAN_N*16) return;
    int node = i >> 4;
    float d = g_dinv[node];
    float4 v = ((const float4*)x)[i];
    g_y4[i] = make_float4(d*v.x, d*v.y, d*v.z, d*v.w);
}

// ---------- K6: fused gather -> W1 -> BN1 -> ReLU -> weighted sum ----------
__global__ void __launch_bounds__(256) k_gnn(const float* __restrict__ W1,
                                             const float* __restrict__ b1,
                                             const float* __restrict__ g1,
                                             const float* __restrict__ be1,
                                             const float* __restrict__ m1,
                                             const float* __restrict__ v1) {
    __shared__ float2 W1p[2][DIN*32];
    __shared__ float  sAcc[8][4][32];
    __shared__ float  sAgg[8][DIN];          // per-warp agg staging
    __shared__ int    sPre[NBLK];
    __shared__ int    sWp[3];
    int tid = threadIdx.x, lane = tid & 31, w = tid >> 5;
    int grp = lane >> 3, l = lane & 7;
    int t = blockIdx.y;

    for (int ii = tid; ii < 2*DIN*32; ii += 256) {
        int p = ii >> 11, rem = ii & 2047;
        int k = rem >> 5, ll = rem & 31;
        W1p[p][k*32 + ll] = make_float2(W1[k*H_ + p*64 + ll],
                                        W1[k*H_ + p*64 + ll + 32]);
    }
    float sc[4], sh[4];
#pragma unroll
    for (int q = 0; q < 4; q++) {
        int j = lane + 32*q;
        float s = g1[j] * rsqrtf(v1[j] + EPSB);
        sc[q] = s;
        sh[q] = (b1[j] - m1[j]) * s + be1[j];
    }
    block_prefix(sPre, sWp, tid);            // has its own __syncthreads

    const unsigned long long* Wp0 = (const unsigned long long*)W1p[0];
    const unsigned long long* Wp1 = (const unsigned long long*)W1p[1];
    const float4* ybase = g_y4 + (size_t)(t*N_)*16;
    float acc[4] = {0.f, 0.f, 0.f, 0.f};

    for (int i = blockIdx.x*8 + w; i < N_; i += gridDim.x*8) {
        int node = t*N_ + i;
        float4 a0, a1;
        if (grp == 0) {
            a0 = ybase[(size_t)i*16 + l];
            a1 = ybase[(size_t)i*16 + l + 8];
        } else {
            a0 = make_float4(0.f, 0.f, 0.f, 0.f);
            a1 = make_float4(0.f, 0.f, 0.f, 0.f);
        }
        int o0 = g_off[node]     + sPre[node >> 11];
        int o1 = g_off[node + 1] + sPre[(node + 1) >> 11];
#pragma unroll 2
        for (int j = o0 + grp; j < o1; j += 4) {
            int s = g_srcs[j];
            const float4* ys = ybase + (size_t)s*16;
            float4 v0 = ys[l], v1 = ys[l + 8];
            a0.x += v0.x; a0.y += v0.y; a0.z += v0.z; a0.w += v0.w;
            a1.x += v1.x; a1.y += v1.y; a1.z += v1.z; a1.w += v1.w;
        }
#pragma unroll
        for (int m = 8; m <= 16; m <<= 1) {
            a0.x += __shfl_xor_sync(0xffffffffu, a0.x, m);
            a0.y += __shfl_xor_sync(0xffffffffu, a0.y, m);
            a0.z += __shfl_xor_sync(0xffffffffu, a0.z, m);
            a0.w += __shfl_xor_sync(0xffffffffu, a0.w, m);
            a1.x += __shfl_xor_sync(0xffffffffu, a1.x, m);
            a1.y += __shfl_xor_sync(0xffffffffu, a1.y, m);
            a1.z += __shfl_xor_sync(0xffffffffu, a1.z, m);
            a1.w += __shfl_xor_sync(0xffffffffu, a1.w, m);
        }
        float ds = g_dinv[node];
        // stage agg in smem: lane l (grp 0's copy == everyone's) holds chunk l / l+8
        if (lane < 8) {
            *(float4*)&sAgg[w][lane*4]       = make_float4(ds*a0.x, ds*a0.y, ds*a0.z, ds*a0.w);
            *(float4*)&sAgg[w][(lane+8)*4]   = make_float4(ds*a1.x, ds*a1.y, ds*a1.z, ds*a1.w);
        }
        __syncwarp();
        unsigned long long p0 = 0ull, p1 = 0ull;
#pragma unroll
        for (int c = 0; c < 16; c++) {
            float4 b = *(const float4*)&sAgg[w][c*4];
            int k = c*4;
            unsigned long long c2;
            c2 = pk2(b.x, b.x); p0 = ffma2(c2, Wp0[(k+0)*32 + lane], p0);
                                p1 = ffma2(c2, Wp1[(k+0)*32 + lane], p1);
            c2 = pk2(b.y, b.y); p0 = ffma2(c2, Wp0[(k+1)*32 + lane], p0);
                                p1 = ffma2(c2, Wp1[(k+1)*32 + lane], p1);
            c2 = pk2(b.z, b.z); p0 = ffma2(c2, Wp0[(k+2)*32 + lane], p0);
                                p1 = ffma2(c2, Wp1[(k+2)*32 + lane], p1);
            c2 = pk2(b.w, b.w); p0 = ffma2(c2, Wp0[(k+3)*32 + lane], p0);
                                p1 = ffma2(c2, Wp1[(k+3)*32 + lane], p1);
        }
        __syncwarp();
        float2 y01 = upk2(p0), y23 = upk2(p1);
        float wi = g_w2[node];
        acc[0] += wi * fmaxf(y01.x*sc[0] + sh[0], 0.f);
        acc[1] += wi * fmaxf(y01.y*sc[1] + sh[1], 0.f);
        acc[2] += wi * fmaxf(y23.x*sc[2] + sh[2], 0.f);
        acc[3] += wi * fmaxf(y23.y*sc[3] + sh[3], 0.f);
    }
#pragma unroll
    for (int q = 0; q < 4; q++) sAcc[w][q][lane] = acc[q];
    __syncthreads();
    if (tid < 128) {
        int q = tid >> 5, ll = tid & 31;
        float s = 0.f;
#pragma unroll
        for (int ww = 0; ww < 8; ww++) s += sAcc[ww][q][ll];
        atomicAdd(&g_S[t*H_ + q*32 + ll], s);
    }
}

__device__ __forceinline__ float sigf(float x) { return 1.f / (1.f + expf(-x)); }

// ---------- K7: finalize ----------
__global__ void __launch_bounds__(512) k_final(const float* __restrict__ W2,
                                               const float* __restrict__ b2,
                                               const float* __restrict__ g2,
                                               const float* __restrict__ be2,
                                               const float* __restrict__ m2,
                                               const float* __restrict__ v2,
                                               const float* __restrict__ Wc,
                                               const float* __restrict__ bc,
                                               float* __restrict__ out) {
    __shared__ float Ssm[T_*H_];
    __shared__ float emb[T_][H_];
    __shared__ float h0[H_], c0[H_], h1[H_], c1[H_];
    __shared__ float gates[512];
    int tid = threadIdx.x;

    for (int i = tid; i < T_*H_; i += 512) Ssm[i] = g_S[i] * (1.0f / N_);
    if (tid < H_) { h0[tid] = 0.f; c0[tid] = 0.f; h1[tid] = 0.f; c1[tid] = 0.f; }
    __syncthreads();

    for (int item = tid; item < T_*H_; item += 512) {
        int t = item >> 7, j = item & 127;
        float s2  = g2[j] * rsqrtf(v2[j] + EPSB);
        float sh2 = be2[j] - m2[j]*s2;
        float acc = b2[j];
#pragma unroll 8
        for (int k = 0; k < H_; k++) acc += Ssm[t*H_ + k] * W2[k*H_ + j];
        emb[t][j] = acc*s2 + sh2;
    }
    __syncthreads();

    int r = tid;
    for (int t = 0; t < T_; t++) {
        float acc = g_bsumL[0][r];
#pragma unroll 8
        for (int k4 = 0; k4 < 32; k4++) {
            float4 wx = g_WT4[0][k4*512 + r];
            float4 wh = g_WT4[1][k4*512 + r];
            int k = k4*4;
            acc += wx.x*emb[t][k] + wx.y*emb[t][k+1] + wx.z*emb[t][k+2] + wx.w*emb[t][k+3];
            acc += wh.x*h0[k]     + wh.y*h0[k+1]     + wh.z*h0[k+2]     + wh.w*h0[k+3];
        }
        gates[r] = acc;
        __syncthreads();
        if (tid < H_) {
            int j = tid;
            float ig = sigf(gates[j]);
            float fg = sigf(gates[H_ + j]);
            float gg = tanhf(gates[2*H_ + j]);
            float og = sigf(gates[3*H_ + j]);
            float cn = fg*c0[j] + ig*gg;
            c0[j] = cn;
            h0[j] = og * tanhf(cn);
        }
        __syncthreads();
        acc = g_bsumL[1][r];
#pragma unroll 8
        for (int k4 = 0; k4 < 32; k4++) {
            float4 wx = g_WT4[2][k4*512 + r];
            float4 wh = g_WT4[3][k4*512 + r];
            int k = k4*4;
            acc += wx.x*h0[k] + wx.y*h0[k+1] + wx.z*h0[k+2] + wx.w*h0[k+3];
            acc += wh.x*h1[k] + wh.y*h1[k+1] + wh.z*h1[k+2] + wh.w*h1[k+3];
        }
        gates[r] = acc;
        __syncthreads();
        if (tid < H_) {
            int j = tid;
            float ig = sigf(gates[j]);
            float fg = sigf(gates[H_ + j]);
            float gg = tanhf(gates[2*H_ + j]);
            float og = sigf(gates[3*H_ + j]);
            float cn = fg*c1[j] + ig*gg;
            c1[j] = cn;
            h1[j] = og * tanhf(cn);
        }
        __syncthreads();
    }

    if (tid < 2) {
        float acc = bc[tid];
#pragma unroll 8
        for (int k = 0; k < H_; k++) acc += Wc[tid*H_ + k] * h1[k];
        out[tid] = acc;
    }
    if (tid < H_) out[2 + tid] = h1[tid];
}

// ---------- launch ----------
extern "C" void kernel_launch(void* const* d_in, const int* in_sizes, int n_in,
                              void* d_out, int out_size) {
    const float* x    = (const float*)d_in[0];
    const int*   ei   = (const int*)  d_in[1];
    const float* W1   = (const float*)d_in[2];
    const float* b1   = (const float*)d_in[3];
    const float* g1   = (const float*)d_in[4];
    const float* be1  = (const float*)d_in[5];
    const float* m1   = (const float*)d_in[6];
    const float* v1   = (const float*)d_in[7];
    const float* W2   = (const float*)d_in[8];
    const float* b2   = (const float*)d_in[9];
    const float* g2   = (const float*)d_in[10];
    const float* be2  = (const float*)d_in[11];
    const float* m2   = (const float*)d_in[12];
    const float* v2   = (const float*)d_in[13];
    const float* Wih0 = (const float*)d_in[14];
    const float* Whh0 = (const float*)d_in[15];
    const float* bih0 = (const float*)d_in[16];
    const float* bhh0 = (const float*)d_in[17];
    const float* Wih1 = (const float*)d_in[18];
    const float* Whh1 = (const float*)d_in[19];
    const float* bih1 = (const float*)d_in[20];
    const float* bhh1 = (const float*)d_in[21];
    const float* Wc   = (const float*)d_in[22];
    const float* bc   = (const float*)d_in[23];

    k_zeroprep<<<(SCAN_N + 255)/256, 256>>>(Wih0, Whh0, Wih1, Whh1,
                                            bih0, bhh0, bih1, bhh1);
    k_count   <<<(TE/4 + 255)/256, 256>>>(ei);
    k_scan1   <<<NBLK, 512>>>();
    k_fill    <<<(TE/4 + 255)/256, 256>>>(ei);
    k_yscale  <<<(SCAN_N*16 + 255)/256, 256>>>(x);
    k_gnn     <<<dim3(74, T_), 256>>>(W1, b1, g1, be1, m1, v1);
    k_final   <<<1, 512>>>(W2, b2, g2, be2, m2, v2, Wc, bc, (float*)d_out);
}

// round 7
// speedup vs baseline: 1.2915x; 1.0246x over previous
#include <cuda_runtime.h>
#include <cuda_bf16.h>
#include <math.h>

#define T_  8
#define N_  20000
#define E_  320000
#define DIN 64
#define H_  128
#define EPSB 1e-5f

#define SCAN_N (T_*N_)
#define SCAN_B 2048
#define NBLK ((SCAN_N + SCAN_B - 1)/SCAN_B)   // 79
#define TE (T_*E_)

// ---------- scratch ----------
__device__ int           g_deg  [SCAN_N];
__device__ float         g_dinv [SCAN_N];
__device__ float         g_w2   [SCAN_N];
__device__ int           g_off  [SCAN_N + 1];   // block-LOCAL offsets
__device__ int           g_cursor[SCAN_N];
__device__ int           g_bsum [NBLK];
__device__ int           g_srcs [TE];
__device__ __nv_bfloat16 g_yb   [(size_t)SCAN_N*64]; // bf16 scaled rows, 128B each
__device__ float         g_S    [T_*H_];
__device__ float4        g_WT4  [4][32*512];
__device__ float         g_bsumL[2][512];

// ---------- helpers ----------
__device__ __forceinline__ unsigned long long pk2(float a, float b) {
    unsigned long long r;
    asm("mov.b64 %0, {%1, %2};" : "=l"(r) : "f"(a), "f"(b));
    return r;
}
__device__ __forceinline__ unsigned long long ffma2(unsigned long long a,
                                                    unsigned long long b,
                                                    unsigned long long c) {
    unsigned long long d;
    asm("fma.rn.f32x2 %0, %1, %2, %3;" : "=l"(d) : "l"(a), "l"(b), "l"(c));
    return d;
}
__device__ __forceinline__ float2 upk2(unsigned long long v) {
    float2 f;
    asm("mov.b64 {%0, %1}, %2;" : "=f"(f.x), "=f"(f.y) : "l"(v));
    return f;
}
__device__ __forceinline__ __nv_bfloat162 asb2(unsigned u) {
    __nv_bfloat162 r; *reinterpret_cast<unsigned*>(&r) = u; return r;
}
__device__ __forceinline__ unsigned asu(__nv_bfloat162 h) {
    return *reinterpret_cast<unsigned*>(&h);
}

// sPre[b] = exclusive prefix over g_bsum[0..b)
__device__ __forceinline__ void block_prefix(int* sPre, int* sWp, int tid) {
    if (tid < 96) {
        int lane = tid & 31;
        int v = (tid < NBLK) ? g_bsum[tid] : 0;
        int incl = v;
#pragma unroll
        for (int d = 1; d < 32; d <<= 1) {
            int n = __shfl_up_sync(0xffffffffu, incl, d);
            if (lane >= d) incl += n;
        }
        if (lane == 31) sWp[tid >> 5] = incl;
        if (tid < NBLK) sPre[tid] = incl - v;
    }
    __syncthreads();
    if (tid < NBLK) {
        int w0 = tid >> 5;
        int c = 0;
        if (w0 > 0) c += sWp[0];
        if (w0 > 1) c += sWp[1];
        sPre[tid] += c;
    }
    __syncthreads();
}

// ---------- K1: in-degree count (int4) + LSTM weight prep (first 256 blocks) ----------
__global__ void k_count(const int* __restrict__ ei,
                        const float* __restrict__ Wih0, const float* __restrict__ Whh0,
                        const float* __restrict__ Wih1, const float* __restrict__ Whh1,
                        const float* __restrict__ bih0, const float* __restrict__ bhh0,
                        const float* __restrict__ bih1, const float* __restrict__ bhh1) {
    int tid = threadIdx.x;
    if (blockIdx.x < 256) {
        int p = blockIdx.x * 256 + tid;              // 0..65535
        if (p < 1024) {
            int L = p >> 9, r = p & 511;
            g_bsumL[L][r] = L ? (bih1[r] + bhh1[r]) : (bih0[r] + bhh0[r]);
        }
        int m = p >> 14, rem = p & 16383;
        int k4 = rem >> 9, r = rem & 511;
        const float* W = (m == 0) ? Wih0 : (m == 1) ? Whh0 : (m == 2) ? Wih1 : Whh1;
        g_WT4[m][k4*512 + r] = ((const float4*)W)[r*32 + k4];
    }
    int i = blockIdx.x * blockDim.x + tid;
    if (i >= TE/4) return;
    int t = i / (E_/4), e4 = i - t*(E_/4);
    int4 d4 = ((const int4*)(ei + t*2*E_ + E_))[e4];
    int base = t*N_;
    atomicAdd(&g_deg[base + d4.x], 1);
    atomicAdd(&g_deg[base + d4.y], 1);
    atomicAdd(&g_deg[base + d4.z], 1);
    atomicAdd(&g_deg[base + d4.w], 1);
}

// ---------- K2: block-local scan + dinv/w2 + bf16 y-scale + zero S ----------
__global__ void __launch_bounds__(512) k_scan1(const float* __restrict__ x) {
    __shared__ int wsum[16];
    int tid = threadIdx.x, lane = tid & 31, w = tid >> 5;
    if (blockIdx.x == 0) {                      // zero S (gnn runs later)
        g_S[tid] = 0.f;
        g_S[tid + 512] = 0.f;
    }
    int base = blockIdx.x*SCAN_B + tid*4;
    int v[4]; int tot = 0;
#pragma unroll
    for (int u = 0; u < 4; u++) {
        v[u] = (base + u < SCAN_N) ? g_deg[base + u] : 0;
        tot += v[u];
    }
#pragma unroll
    for (int u = 0; u < 4; u++) {
        if (base + u < SCAN_N) {
            float d = rsqrtf(1.0f + (float)v[u]);
            g_dinv[base + u] = d;
            g_w2[base + u]   = d * d;
        }
    }
    int incl = tot;
#pragma unroll
    for (int d = 1; d < 32; d <<= 1) {
        int n = __shfl_up_sync(0xffffffffu, incl, d);
        if (lane >= d) incl += n;
    }
    int excl = incl - tot;
    if (lane == 31) wsum[w] = incl;
    __syncthreads();
    if (w == 0) {
        int s = (lane < 16) ? wsum[lane] : 0;
        int inc = s;
#pragma unroll
        for (int d = 1; d < 32; d <<= 1) {
            int n = __shfl_up_sync(0xffffffffu, inc, d);
            if (lane >= d) inc += n;
        }
        if (lane < 16) wsum[lane] = inc - s;
    }
    __syncthreads();
    int run = excl + wsum[w];
#pragma unroll
    for (int u = 0; u < 4; u++) {
        if (base + u <= SCAN_N) {
            g_off[base + u] = run;
            if (base + u < SCAN_N) g_cursor[base + u] = run;
        }
        run += v[u];
    }
    if (tid == 511) g_bsum[blockIdx.x] = run;

    // ---- bf16 y-scale for this block's 2048 nodes ----
    int nb0 = blockIdx.x*SCAN_B;
    const float4* x4 = (const float4*)x;
    for (int ci = tid; ci < SCAN_B*16; ci += 512) {
        int node = nb0 + (ci >> 4);
        if (node >= SCAN_N) break;
        float d = rsqrtf(1.0f + (float)g_deg[node]);
        float4 vv = x4[(size_t)node*16 + (ci & 15)];
        __nv_bfloat162 p0 = __floats2bfloat162_rn(d*vv.x, d*vv.y);
        __nv_bfloat162 p1 = __floats2bfloat162_rn(d*vv.z, d*vv.w);
        uint2 st; st.x = asu(p0); st.y = asu(p1);
        ((uint2*)(g_yb + (size_t)node*64))[ci & 15] = st;
    }
}

// ---------- K3: fill CSR + w2 scatter ----------
__global__ void __launch_bounds__(256) k_fill(const int* __restrict__ ei) {
    __shared__ int sPre[NBLK];
    __shared__ int sWp[3];
    int tid = threadIdx.x;
    block_prefix(sPre, sWp, tid);

    int i = blockIdx.x*256 + tid;
    if (i >= TE/4) return;
    int t = i / (E_/4), e4 = i - t*(E_/4);
    int4 s4 = ((const int4*)(ei + t*2*E_))[e4];
    int4 d4 = ((const int4*)(ei + t*2*E_ + E_))[e4];
    int base = t*N_;
#pragma unroll
    for (int u = 0; u < 4; u++) {
        int src = (u == 0) ? s4.x : (u == 1) ? s4.y : (u == 2) ? s4.z : s4.w;
        int dst = (u == 0) ? d4.x : (u == 1) ? d4.y : (u == 2) ? d4.z : d4.w;
        int ns = base + src, nd = base + dst;
        float c = g_dinv[ns] * g_dinv[nd];
        atomicAdd(&g_w2[ns], c);
        int pos = atomicAdd(&g_cursor[nd], 1) + sPre[nd >> 11];
        g_srcs[pos] = src;
    }
}

// ---------- K4 (PROFILE SLOT): gather(bf16) -> W1 -> BN1 -> ReLU -> weighted sum ----------
__global__ void __launch_bounds__(256) k_gnn(const float* __restrict__ W1,
                                             const float* __restrict__ b1,
                                             const float* __restrict__ g1,
                                             const float* __restrict__ be1,
                                             const float* __restrict__ m1,
                                             const float* __restrict__ v1) {
    __shared__ float2 W1p[2][DIN*32];
    __shared__ float  sAcc[8][4][32];
    __shared__ float  sAgg[8][DIN];
    __shared__ int    sPre[NBLK];
    __shared__ int    sWp[3];
    int tid = threadIdx.x, lane = tid & 31, w = tid >> 5;
    int grp = lane >> 3, l = lane & 7;
    int t = blockIdx.y;

    for (int ii = tid; ii < 2*DIN*32; ii += 256) {
        int p = ii >> 11, rem = ii & 2047;
        int k = rem >> 5, ll = rem & 31;
        W1p[p][k*32 + ll] = make_float2(W1[k*H_ + p*64 + ll],
                                        W1[k*H_ + p*64 + ll + 32]);
    }
    float sc[4], sh[4];
#pragma unroll
    for (int q = 0; q < 4; q++) {
        int j = lane + 32*q;
        float s = g1[j] * rsqrtf(v1[j] + EPSB);
        sc[q] = s;
        sh[q] = (b1[j] - m1[j]) * s + be1[j];
    }
    block_prefix(sPre, sWp, tid);

    const unsigned long long* Wp0 = (const unsigned long long*)W1p[0];
    const unsigned long long* Wp1 = (const unsigned long long*)W1p[1];
    const uint4* yb4 = (const uint4*)(g_yb + (size_t)(t*N_)*64);  // 8 uint4 per row
    float acc[4] = {0.f, 0.f, 0.f, 0.f};

    for (int i = blockIdx.x*8 + w; i < N_; i += gridDim.x*8) {
        int node = t*N_ + i;
        __nv_bfloat162 A0, A1, A2, A3;
        if (grp == 0) {
            uint4 sv = yb4[(size_t)i*8 + l];
            A0 = asb2(sv.x); A1 = asb2(sv.y); A2 = asb2(sv.z); A3 = asb2(sv.w);
        } else {
            A0 = A1 = A2 = A3 = asb2(0u);
        }
        int o0 = g_off[node]     + sPre[node >> 11];
        int o1 = g_off[node + 1] + sPre[(node + 1) >> 11];
#pragma unroll 2
        for (int j = o0 + grp; j < o1; j += 4) {
            int s = g_srcs[j];
            uint4 vv = yb4[(size_t)s*8 + l];
            A0 = __hadd2(A0, asb2(vv.x));
            A1 = __hadd2(A1, asb2(vv.y));
            A2 = __hadd2(A2, asb2(vv.z));
            A3 = __hadd2(A3, asb2(vv.w));
        }
#pragma unroll
        for (int m = 8; m <= 16; m <<= 1) {
            A0 = __hadd2(A0, asb2(__shfl_xor_sync(0xffffffffu, asu(A0), m)));
            A1 = __hadd2(A1, asb2(__shfl_xor_sync(0xffffffffu, asu(A1), m)));
            A2 = __hadd2(A2, asb2(__shfl_xor_sync(0xffffffffu, asu(A2), m)));
            A3 = __hadd2(A3, asb2(__shfl_xor_sync(0xffffffffu, asu(A3), m)));
        }
        float ds = g_dinv[node];
        if (lane < 8) {
            float2 f0 = __bfloat1622float2(A0);
            float2 f1 = __bfloat1622float2(A1);
            float2 f2 = __bfloat1622float2(A2);
            float2 f3 = __bfloat1622float2(A3);
            *(float4*)&sAgg[w][lane*8]     = make_float4(ds*f0.x, ds*f0.y, ds*f1.x, ds*f1.y);
            *(float4*)&sAgg[w][lane*8 + 4] = make_float4(ds*f2.x, ds*f2.y, ds*f3.x, ds*f3.y);
        }
        __syncwarp();
        unsigned long long p0 = 0ull, p1 = 0ull;
#pragma unroll
        for (int c = 0; c < 16; c++) {
            float4 b = *(const float4*)&sAgg[w][c*4];
            int k = c*4;
            unsigned long long c2;
            c2 = pk2(b.x, b.x); p0 = ffma2(c2, Wp0[(k+0)*32 + lane], p0);
                                p1 = ffma2(c2, Wp1[(k+0)*32 + lane], p1);
            c2 = pk2(b.y, b.y); p0 = ffma2(c2, Wp0[(k+1)*32 + lane], p0);
                                p1 = ffma2(c2, Wp1[(k+1)*32 + lane], p1);
            c2 = pk2(b.z, b.z); p0 = ffma2(c2, Wp0[(k+2)*32 + lane], p0);
                                p1 = ffma2(c2, Wp1[(k+2)*32 + lane], p1);
            c2 = pk2(b.w, b.w); p0 = ffma2(c2, Wp0[(k+3)*32 + lane], p0);
                                p1 = ffma2(c2, Wp1[(k+3)*32 + lane], p1);
        }
        __syncwarp();
        float2 y01 = upk2(p0), y23 = upk2(p1);
        float wi = g_w2[node];
        acc[0] += wi * fmaxf(y01.x*sc[0] + sh[0], 0.f);
        acc[1] += wi * fmaxf(y01.y*sc[1] + sh[1], 0.f);
        acc[2] += wi * fmaxf(y23.x*sc[2] + sh[2], 0.f);
        acc[3] += wi * fmaxf(y23.y*sc[3] + sh[3], 0.f);
    }
#pragma unroll
    for (int q = 0; q < 4; q++) sAcc[w][q][lane] = acc[q];
    __syncthreads();
    if (tid < 128) {
        int q = tid >> 5, ll = tid & 31;
        float s = 0.f;
#pragma unroll
        for (int ww = 0; ww < 8; ww++) s += sAcc[ww][q][ll];
        atomicAdd(&g_S[t*H_ + q*32 + ll], s);
    }
}

__device__ __forceinline__ float sigf(float x) { return 1.f / (1.f + expf(-x)); }

// ---------- K5: finalize ----------
__global__ void __launch_bounds__(512) k_final(const float* __restrict__ W2,
                                               const float* __restrict__ b2,
                                               const float* __restrict__ g2,
                                               const float* __restrict__ be2,
                                               const float* __restrict__ m2,
                                               const float* __restrict__ v2,
                                               const float* __restrict__ Wc,
                                               const float* __restrict__ bc,
                                               float* __restrict__ out) {
    __shared__ float Ssm[T_*H_];
    __shared__ float emb[T_][H_];
    __shared__ float h0[H_], c0[H_], h1[H_], c1[H_];
    __shared__ float gates[512];
    int tid = threadIdx.x;

    for (int i = tid; i < T_*H_; i += 512) Ssm[i] = g_S[i] * (1.0f / N_);
    if (tid < H_) { h0[tid] = 0.f; c0[tid] = 0.f; h1[tid] = 0.f; c1[tid] = 0.f; }
    __syncthreads();

    for (int item = tid; item < T_*H_; item += 512) {
        int t = item >> 7, j = item & 127;
        float s2  = g2[j] * rsqrtf(v2[j] + EPSB);
        float sh2 = be2[j] - m2[j]*s2;
        float acc = b2[j];
#pragma unroll 8
        for (int k = 0; k < H_; k++) acc += Ssm[t*H_ + k] * W2[k*H_ + j];
        emb[t][j] = acc*s2 + sh2;
    }
    __syncthreads();

    int r = tid;
    for (int t = 0; t < T_; t++) {
        float acc = g_bsumL[0][r];
#pragma unroll 8
        for (int k4 = 0; k4 < 32; k4++) {
            float4 wx = g_WT4[0][k4*512 + r];
            float4 wh = g_WT4[1][k4*512 + r];
            int k = k4*4;
            acc += wx.x*emb[t][k] + wx.y*emb[t][k+1] + wx.z*emb[t][k+2] + wx.w*emb[t][k+3];
            acc += wh.x*h0[k]     + wh.y*h0[k+1]     + wh.z*h0[k+2]     + wh.w*h0[k+3];
        }
        gates[r] = acc;
        __syncthreads();
        if (tid < H_) {
            int j = tid;
            float ig = sigf(gates[j]);
            float fg = sigf(gates[H_ + j]);
            float gg = tanhf(gates[2*H_ + j]);
            float og = sigf(gates[3*H_ + j]);
            float cn = fg*c0[j] + ig*gg;
            c0[j] = cn;
            h0[j] = og * tanhf(cn);
        }
        __syncthreads();
        acc = g_bsumL[1][r];
#pragma unroll 8
        for (int k4 = 0; k4 < 32; k4++) {
            float4 wx = g_WT4[2][k4*512 + r];
            float4 wh = g_WT4[3][k4*512 + r];
            int k = k4*4;
            acc += wx.x*h0[k] + wx.y*h0[k+1] + wx.z*h0[k+2] + wx.w*h0[k+3];
            acc += wh.x*h1[k] + wh.y*h1[k+1] + wh.z*h1[k+2] + wh.w*h1[k+3];
        }
        gates[r] = acc;
        __syncthreads();
        if (tid < H_) {
            int j = tid;
            float ig = sigf(gates[j]);
            float fg = sigf(gates[H_ + j]);
            float gg = tanhf(gates[2*H_ + j]);
            float og = sigf(gates[3*H_ + j]);
            float cn = fg*c1[j] + ig*gg;
            c1[j] = cn;
            h1[j] = og * tanhf(cn);
        }
        __syncthreads();
    }

    if (tid < 2) {
        float acc = bc[tid];
#pragma unroll 8
        for (int k = 0; k < H_; k++) acc += Wc[tid*H_ + k] * h1[k];
        out[tid] = acc;
    }
    if (tid < H_) out[2 + tid] = h1[tid];
}

// ---------- launch ----------
extern "C" void kernel_launch(void* const* d_in, const int* in_sizes, int n_in,
                              void* d_out, int out_size) {
    const float* x    = (const float*)d_in[0];
    const int*   ei   = (const int*)  d_in[1];
    const float* W1   = (const float*)d_in[2];
    const float* b1   = (const float*)d_in[3];
    const float* g1   = (const float*)d_in[4];
    const float* be1  = (const float*)d_in[5];
    const float* m1   = (const float*)d_in[6];
    const float* v1   = (const float*)d_in[7];
    const float* W2   = (const float*)d_in[8];
    const float* b2   = (const float*)d_in[9];
    const float* g2   = (const float*)d_in[10];
    const float* be2  = (const float*)d_in[11];
    const float* m2   = (const float*)d_in[12];
    const float* v2   = (const float*)d_in[13];
    const float* Wih0 = (const float*)d_in[14];
    const float* Whh0 = (const float*)d_in[15];
    const float* bih0 = (const float*)d_in[16];
    const float* bhh0 = (const float*)d_in[17];
    const float* Wih1 = (const float*)d_in[18];
    const float* Whh1 = (const float*)d_in[19];
    const float* bih1 = (const float*)d_in[20];
    const float* bhh1 = (const float*)d_in[21];
    const float* Wc   = (const float*)d_in[22];
    const float* bc   = (const float*)d_in[23];

    void* degp = nullptr;
    cudaGetSymbolAddress(&degp, g_deg);
    cudaMemsetAsync(degp, 0, SCAN_N * sizeof(int));

    k_count<<<(TE/4 + 255)/256, 256>>>(ei, Wih0, Whh0, Wih1, Whh1,
                                       bih0, bhh0, bih1, bhh1);
    k_scan1<<<NBLK, 512>>>(x);
    k_fill <<<(TE/4 + 255)/256, 256>>>(ei);
    k_gnn  <<<dim3(74, T_), 256>>>(W1, b1, g1, be1, m1, v1);
    k_final<<<1, 512>>>(W2, b2, g2, be2, m2, v2, Wc, bc, (float*)d_out);
}

// round 9
// speedup vs baseline: 1.4188x; 1.0986x over previous
#include <cuda_runtime.h>
#include <cuda_bf16.h>
#include <math.h>

#define T_  8
#define N_  20000
#define E_  320000
#define DIN 64
#define H_  128
#define EPSB 1e-5f

#define SCAN_N (T_*N_)
#define SCAN_B 2048
#define NBLK ((SCAN_N + SCAN_B - 1)/SCAN_B)   // 79
#define TE (T_*E_)
#define NB 8                                   // nodes per warp per matmul pass

// ---------- scratch ----------
__device__ int           g_deg  [SCAN_N];
__device__ float         g_dinv [SCAN_N];
__device__ float         g_w2   [SCAN_N];
__device__ int           g_off  [SCAN_N + 1];   // block-LOCAL offsets
__device__ int           g_cursor[SCAN_N];
__device__ int           g_bsum [NBLK];
__device__ int           g_srcs [TE];
__device__ __nv_bfloat16 g_yb   [(size_t)SCAN_N*64]; // bf16 scaled rows, 128B each
__device__ float         g_S    [T_*H_];
__device__ float4        g_WT4  [4][32*512];
__device__ float         g_bsumL[2][512];

// ---------- helpers ----------
__device__ __forceinline__ unsigned long long pk2(float a, float b) {
    unsigned long long r;
    asm("mov.b64 %0, {%1, %2};" : "=l"(r) : "f"(a), "f"(b));
    return r;
}
__device__ __forceinline__ unsigned long long ffma2(unsigned long long a,
                                                    unsigned long long b,
                                                    unsigned long long c) {
    unsigned long long d;
    asm("fma.rn.f32x2 %0, %1, %2, %3;" : "=l"(d) : "l"(a), "l"(b), "l"(c));
    return d;
}
__device__ __forceinline__ float2 upk2(unsigned long long v) {
    float2 f;
    asm("mov.b64 {%0, %1}, %2;" : "=f"(f.x), "=f"(f.y) : "l"(v));
    return f;
}
__device__ __forceinline__ __nv_bfloat162 asb2(unsigned u) {
    __nv_bfloat162 r; *reinterpret_cast<unsigned*>(&r) = u; return r;
}
__device__ __forceinline__ unsigned asu(__nv_bfloat162 h) {
    return *reinterpret_cast<unsigned*>(&h);
}

// sPre[b] = exclusive prefix over g_bsum[0..b)
__device__ __forceinline__ void block_prefix(int* sPre, int* sWp, int tid) {
    if (tid < 96) {
        int lane = tid & 31;
        int v = (tid < NBLK) ? g_bsum[tid] : 0;
        int incl = v;
#pragma unroll
        for (int d = 1; d < 32; d <<= 1) {
            int n = __shfl_up_sync(0xffffffffu, incl, d);
            if (lane >= d) incl += n;
        }
        if (lane == 31) sWp[tid >> 5] = incl;
        if (tid < NBLK) sPre[tid] = incl - v;
    }
    __syncthreads();
    if (tid < NBLK) {
        int w0 = tid >> 5;
        int c = 0;
        if (w0 > 0) c += sWp[0];
        if (w0 > 1) c += sWp[1];
        sPre[tid] += c;
    }
    __syncthreads();
}

// ---------- K1: in-degree count (int4) + LSTM weight prep ----------
__global__ void k_count(const int* __restrict__ ei,
                        const float* __restrict__ Wih0, const float* __restrict__ Whh0,
                        const float* __restrict__ Wih1, const float* __restrict__ Whh1,
                        const float* __restrict__ bih0, const float* __restrict__ bhh0,
                        const float* __restrict__ bih1, const float* __restrict__ bhh1) {
    int tid = threadIdx.x;
    if (blockIdx.x < 256) {
        int p = blockIdx.x * 256 + tid;              // 0..65535
        if (p < 1024) {
            int L = p >> 9, r = p & 511;
            g_bsumL[L][r] = L ? (bih1[r] + bhh1[r]) : (bih0[r] + bhh0[r]);
        }
        int m = p >> 14, rem = p & 16383;
        int k4 = rem >> 9, r = rem & 511;
        const float* W = (m == 0) ? Wih0 : (m == 1) ? Whh0 : (m == 2) ? Wih1 : Whh1;
        g_WT4[m][k4*512 + r] = ((const float4*)W)[r*32 + k4];
    }
    int i = blockIdx.x * blockDim.x + tid;
    if (i >= TE/4) return;
    int t = i / (E_/4), e4 = i - t*(E_/4);
    int4 d4 = ((const int4*)(ei + t*2*E_ + E_))[e4];
    int base = t*N_;
    atomicAdd(&g_deg[base + d4.x], 1);
    atomicAdd(&g_deg[base + d4.y], 1);
    atomicAdd(&g_deg[base + d4.z], 1);
    atomicAdd(&g_deg[base + d4.w], 1);
}

// ---------- K2: block-local scan + dinv/w2 + bf16 y-scale + zero S ----------
__global__ void __launch_bounds__(512) k_scan1(const float* __restrict__ x) {
    __shared__ int wsum[16];
    int tid = threadIdx.x, lane = tid & 31, w = tid >> 5;
    if (blockIdx.x == 0) {
        g_S[tid] = 0.f;
        g_S[tid + 512] = 0.f;
    }
    int base = blockIdx.x*SCAN_B + tid*4;
    int v[4]; int tot = 0;
#pragma unroll
    for (int u = 0; u < 4; u++) {
        v[u] = (base + u < SCAN_N) ? g_deg[base + u] : 0;
        tot += v[u];
    }
#pragma unroll
    for (int u = 0; u < 4; u++) {
        if (base + u < SCAN_N) {
            float d = rsqrtf(1.0f + (float)v[u]);
            g_dinv[base + u] = d;
            g_w2[base + u]   = d * d;
        }
    }
    int incl = tot;
#pragma unroll
    for (int d = 1; d < 32; d <<= 1) {
        int n = __shfl_up_sync(0xffffffffu, incl, d);
        if (lane >= d) incl += n;
    }
    int excl = incl - tot;
    if (lane == 31) wsum[w] = incl;
    __syncthreads();
    if (w == 0) {
        int s = (lane < 16) ? wsum[lane] : 0;
        int inc = s;
#pragma unroll
        for (int d = 1; d < 32; d <<= 1) {
            int n = __shfl_up_sync(0xffffffffu, inc, d);
            if (lane >= d) inc += n;
        }
        if (lane < 16) wsum[lane] = inc - s;
    }
    __syncthreads();
    int run = excl + wsum[w];
#pragma unroll
    for (int u = 0; u < 4; u++) {
        if (base + u <= SCAN_N) {
            g_off[base + u] = run;
            if (base + u < SCAN_N) g_cursor[base + u] = run;
        }
        run += v[u];
    }
    if (tid == 511) g_bsum[blockIdx.x] = run;

    int nb0 = blockIdx.x*SCAN_B;
    const float4* x4 = (const float4*)x;
    for (int ci = tid; ci < SCAN_B*16; ci += 512) {
        int node = nb0 + (ci >> 4);
        if (node >= SCAN_N) break;
        float d = rsqrtf(1.0f + (float)g_deg[node]);
        float4 vv = x4[(size_t)node*16 + (ci & 15)];
        __nv_bfloat162 p0 = __floats2bfloat162_rn(d*vv.x, d*vv.y);
        __nv_bfloat162 p1 = __floats2bfloat162_rn(d*vv.z, d*vv.w);
        uint2 st; st.x = asu(p0); st.y = asu(p1);
        ((uint2*)(g_yb + (size_t)node*64))[ci & 15] = st;
    }
}

// ---------- K3: fill CSR + w2 scatter ----------
__global__ void __launch_bounds__(256) k_fill(const int* __restrict__ ei) {
    __shared__ int sPre[NBLK];
    __shared__ int sWp[3];
    int tid = threadIdx.x;
    block_prefix(sPre, sWp, tid);

    int i = blockIdx.x*256 + tid;
    if (i >= TE/4) return;
    int t = i / (E_/4), e4 = i - t*(E_/4);
    int4 s4 = ((const int4*)(ei + t*2*E_))[e4];
    int4 d4 = ((const int4*)(ei + t*2*E_ + E_))[e4];
    int base = t*N_;
#pragma unroll
    for (int u = 0; u < 4; u++) {
        int src = (u == 0) ? s4.x : (u == 1) ? s4.y : (u == 2) ? s4.z : s4.w;
        int dst = (u == 0) ? d4.x : (u == 1) ? d4.y : (u == 2) ? d4.z : d4.w;
        int ns = base + src, nd = base + dst;
        float c = g_dinv[ns] * g_dinv[nd];
        atomicAdd(&g_w2[ns], c);
        int pos = atomicAdd(&g_cursor[nd], 1) + sPre[nd >> 11];
        g_srcs[pos] = src;
    }
}

// ---------- K4 (PROFILE SLOT): gather(bf16) -> node-blocked W1 matmul -> BN1 -> ReLU -> weighted sum ----------
__global__ void __launch_bounds__(256) k_gnn(const float* __restrict__ W1,
                                             const float* __restrict__ b1,
                                             const float* __restrict__ g1,
                                             const float* __restrict__ be1,
                                             const float* __restrict__ m1,
                                             const float* __restrict__ v1) {
    __shared__ float2 W1p[2][DIN*32];          // 32KB
    __shared__ float  sAcc[8][4][32];          // 4KB
    __shared__ float  sAgg[8][NB][DIN];        // 16KB: per-warp, per-node agg
    __shared__ int    sPre[NBLK];
    __shared__ int    sWp[3];
    int tid = threadIdx.x, lane = tid & 31, w = tid >> 5;
    int grp = lane >> 3, l = lane & 7;
    int t = blockIdx.y;

    for (int ii = tid; ii < 2*DIN*32; ii += 256) {
        int p = ii >> 11, rem = ii & 2047;
        int k = rem >> 5, ll = rem & 31;
        W1p[p][k*32 + ll] = make_float2(W1[k*H_ + p*64 + ll],
                                        W1[k*H_ + p*64 + ll + 32]);
    }
    float sc[4], sh[4];
#pragma unroll
    for (int q = 0; q < 4; q++) {
        int j = lane + 32*q;
        float s = g1[j] * rsqrtf(v1[j] + EPSB);
        sc[q] = s;
        sh[q] = (b1[j] - m1[j]) * s + be1[j];
    }
    block_prefix(sPre, sWp, tid);

    const unsigned long long* Wp0 = (const unsigned long long*)W1p[0];
    const unsigned long long* Wp1 = (const unsigned long long*)W1p[1];
    const uint4* yb4 = (const uint4*)(g_yb + (size_t)(t*N_)*64);
    float acc[4] = {0.f, 0.f, 0.f, 0.f};

    int stride = gridDim.x * 8 * NB;
    for (int i0 = (blockIdx.x*8 + w)*NB; i0 < N_; i0 += stride) {
        // ---- phase 1: gather NB nodes into sAgg[w] ----
#pragma unroll
        for (int u = 0; u < NB; u++) {
            int iu = min(i0 + u, N_ - 1);
            int node = t*N_ + iu;
            __nv_bfloat162 A0, A1, A2, A3;
            if (grp == 0) {
                uint4 sv = yb4[(size_t)iu*8 + l];
                A0 = asb2(sv.x); A1 = asb2(sv.y); A2 = asb2(sv.z); A3 = asb2(sv.w);
            } else {
                A0 = A1 = A2 = A3 = asb2(0u);
            }
            int o0 = g_off[node]     + sPre[node >> 11];
            int o1 = g_off[node + 1] + sPre[(node + 1) >> 11];
#pragma unroll 2
            for (int j = o0 + grp; j < o1; j += 4) {
                int s = g_srcs[j];
                uint4 vv = yb4[(size_t)s*8 + l];
                A0 = __hadd2(A0, asb2(vv.x));
                A1 = __hadd2(A1, asb2(vv.y));
                A2 = __hadd2(A2, asb2(vv.z));
                A3 = __hadd2(A3, asb2(vv.w));
            }
#pragma unroll
            for (int m = 8; m <= 16; m <<= 1) {
                A0 = __hadd2(A0, asb2(__shfl_xor_sync(0xffffffffu, asu(A0), m)));
                A1 = __hadd2(A1, asb2(__shfl_xor_sync(0xffffffffu, asu(A1), m)));
                A2 = __hadd2(A2, asb2(__shfl_xor_sync(0xffffffffu, asu(A2), m)));
                A3 = __hadd2(A3, asb2(__shfl_xor_sync(0xffffffffu, asu(A3), m)));
            }
            float ds = g_dinv[node];
            if (lane < 8) {
                float2 f0 = __bfloat1622float2(A0);
                float2 f1 = __bfloat1622float2(A1);
                float2 f2 = __bfloat1622float2(A2);
                float2 f3 = __bfloat1622float2(A3);
                *(float4*)&sAgg[w][u][lane*8]     = make_float4(ds*f0.x, ds*f0.y, ds*f1.x, ds*f1.y);
                *(float4*)&sAgg[w][u][lane*8 + 4] = make_float4(ds*f2.x, ds*f2.y, ds*f3.x, ds*f3.y);
            }
        }
        __syncwarp();

        // ---- phase 2: matmul NB nodes sharing every W fragment ----
        unsigned long long P0[NB], P1[NB];
#pragma unroll
        for (int u = 0; u < NB; u++) { P0[u] = 0ull; P1[u] = 0ull; }
#pragma unroll 4
        for (int c = 0; c < 16; c++) {
            int k = c*4;
            unsigned long long w00 = Wp0[(k+0)*32 + lane];
            unsigned long long w01 = Wp0[(k+1)*32 + lane];
            unsigned long long w02 = Wp0[(k+2)*32 + lane];
            unsigned long long w03 = Wp0[(k+3)*32 + lane];
            unsigned long long w10 = Wp1[(k+0)*32 + lane];
            unsigned long long w11 = Wp1[(k+1)*32 + lane];
            unsigned long long w12 = Wp1[(k+2)*32 + lane];
            unsigned long long w13 = Wp1[(k+3)*32 + lane];
#pragma unroll
            for (int u = 0; u < NB; u++) {
                float4 b = *(const float4*)&sAgg[w][u][c*4];
                unsigned long long c2;
                c2 = pk2(b.x, b.x); P0[u] = ffma2(c2, w00, P0[u]);
                                    P1[u] = ffma2(c2, w10, P1[u]);
                c2 = pk2(b.y, b.y); P0[u] = ffma2(c2, w01, P0[u]);
                                    P1[u] = ffma2(c2, w11, P1[u]);
                c2 = pk2(b.z, b.z); P0[u] = ffma2(c2, w02, P0[u]);
                                    P1[u] = ffma2(c2, w12, P1[u]);
                c2 = pk2(b.w, b.w); P0[u] = ffma2(c2, w03, P0[u]);
                                    P1[u] = ffma2(c2, w13, P1[u]);
            }
        }
        __syncwarp();

        // ---- epilogue: BN + ReLU + weighted accumulate ----
#pragma unroll
        for (int u = 0; u < NB; u++) {
            int iu = i0 + u;
            float wi = (iu < N_) ? g_w2[t*N_ + iu] : 0.f;
            float2 y01 = upk2(P0[u]), y23 = upk2(P1[u]);
            acc[0] += wi * fmaxf(y01.x*sc[0] + sh[0], 0.f);
            acc[1] += wi * fmaxf(y01.y*sc[1] + sh[1], 0.f);
            acc[2] += wi * fmaxf(y23.x*sc[2] + sh[2], 0.f);
            acc[3] += wi * fmaxf(y23.y*sc[3] + sh[3], 0.f);
        }
    }
#pragma unroll
    for (int q = 0; q < 4; q++) sAcc[w][q][lane] = acc[q];
    __syncthreads();
    if (tid < 128) {
        int q = tid >> 5, ll = tid & 31;
        float s = 0.f;
#pragma unroll
        for (int ww = 0; ww < 8; ww++) s += sAcc[ww][q][ll];
        atomicAdd(&g_S[t*H_ + q*32 + ll], s);
    }
}

__device__ __forceinline__ float sigf(float x) { return 1.f / (1.f + expf(-x)); }

// ---------- K5: finalize ----------
__global__ void __launch_bounds__(512) k_final(const float* __restrict__ W2,
                                               const float* __restrict__ b2,
                                               const float* __restrict__ g2,
                                               const float* __restrict__ be2,
                                               const float* __restrict__ m2,
                                               const float* __restrict__ v2,
                                               const float* __restrict__ Wc,
                                               const float* __restrict__ bc,
                                               float* __restrict__ out) {
    __shared__ float Ssm[T_*H_];
    __shared__ float emb[T_][H_];
    __shared__ float h0[H_], c0[H_], h1[H_], c1[H_];
    __shared__ float gates[512];
    int tid = threadIdx.x;

    for (int i = tid; i < T_*H_; i += 512) Ssm[i] = g_S[i] * (1.0f / N_);
    if (tid < H_) { h0[tid] = 0.f; c0[tid] = 0.f; h1[tid] = 0.f; c1[tid] = 0.f; }
    __syncthreads();

    for (int item = tid; item < T_*H_; item += 512) {
        int t = item >> 7, j = item & 127;
        float s2  = g2[j] * rsqrtf(v2[j] + EPSB);
        float sh2 = be2[j] - m2[j]*s2;
        float acc = b2[j];
#pragma unroll 8
        for (int k = 0; k < H_; k++) acc += Ssm[t*H_ + k] * W2[k*H_ + j];
        emb[t][j] = acc*s2 + sh2;
    }
    __syncthreads();

    int r = tid;
    for (int t = 0; t < T_; t++) {
        float acc = g_bsumL[0][r];
#pragma unroll 8
        for (int k4 = 0; k4 < 32; k4++) {
            float4 wx = g_WT4[0][k4*512 + r];
            float4 wh = g_WT4[1][k4*512 + r];
            int k = k4*4;
            acc += wx.x*emb[t][k] + wx.y*emb[t][k+1] + wx.z*emb[t][k+2] + wx.w*emb[t][k+3];
            acc += wh.x*h0[k]     + wh.y*h0[k+1]     + wh.z*h0[k+2]     + wh.w*h0[k+3];
        }
        gates[r] = acc;
        __syncthreads();
        if (tid < H_) {
            int j = tid;
            float ig = sigf(gates[j]);
            float fg = sigf(gates[H_ + j]);
            float gg = tanhf(gates[2*H_ + j]);
            float og = sigf(gates[3*H_ + j]);
            float cn = fg*c0[j] + ig*gg;
            c0[j] = cn;
            h0[j] = og * tanhf(cn);
        }
        __syncthreads();
        acc = g_bsumL[1][r];
#pragma unroll 8
        for (int k4 = 0; k4 < 32; k4++) {
            float4 wx = g_WT4[2][k4*512 + r];
            float4 wh = g_WT4[3][k4*512 + r];
            int k = k4*4;
            acc += wx.x*h0[k] + wx.y*h0[k+1] + wx.z*h0[k+2] + wx.w*h0[k+3];
            acc += wh.x*h1[k] + wh.y*h1[k+1] + wh.z*h1[k+2] + wh.w*h1[k+3];
        }
        gates[r] = acc;
        __syncthreads();
        if (tid < H_) {
            int j = tid;
            float ig = sigf(gates[j]);
            float fg = sigf(gates[H_ + j]);
            float gg = tanhf(gates[2*H_ + j]);
            float og = sigf(gates[3*H_ + j]);
            float cn = fg*c1[j] + ig*gg;
            c1[j] = cn;
            h1[j] = og * tanhf(cn);
        }
        __syncthreads();
    }

    if (tid < 2) {
        float acc = bc[tid];
#pragma unroll 8
        for (int k = 0; k < H_; k++) acc += Wc[tid*H_ + k] * h1[k];
        out[tid] = acc;
    }
    if (tid < H_) out[2 + tid] = h1[tid];
}

// ---------- launch ----------
extern "C" void kernel_launch(void* const* d_in, const int* in_sizes, int n_in,
                              void* d_out, int out_size) {
    const float* x    = (const float*)d_in[0];
    const int*   ei   = (const int*)  d_in[1];
    const float* W1   = (const float*)d_in[2];
    const float* b1   = (const float*)d_in[3];
    const float* g1   = (const float*)d_in[4];
    const float* be1  = (const float*)d_in[5];
    const float* m1   = (const float*)d_in[6];
    const float* v1   = (const float*)d_in[7];
    const float* W2   = (const float*)d_in[8];
    const float* b2   = (const float*)d_in[9];
    const float* g2   = (const float*)d_in[10];
    const float* be2  = (const float*)d_in[11];
    const float* m2   = (const float*)d_in[12];
    const float* v2   = (const float*)d_in[13];
    const float* Wih0 = (const float*)d_in[14];
    const float* Whh0 = (const float*)d_in[15];
    const float* bih0 = (const float*)d_in[16];
    const float* bhh0 = (const float*)d_in[17];
    const float* Wih1 = (const float*)d_in[18];
    const float* Whh1 = (const float*)d_in[19];
    const float* bih1 = (const float*)d_in[20];
    const float* bhh1 = (const float*)d_in[21];
    const float* Wc   = (const float*)d_in[22];
    const float* bc   = (const float*)d_in[23];

    void* degp = nullptr;
    cudaGetSymbolAddress(&degp, g_deg);
    cudaMemsetAsync(degp, 0, SCAN_N * sizeof(int));

    k_count<<<(TE/4 + 255)/256, 256>>>(ei, Wih0, Whh0, Wih1, Whh1,
                                       bih0, bhh0, bih1, bhh1);
    k_scan1<<<NBLK, 512>>>(x);
    k_fill <<<(TE/4 + 255)/256, 256>>>(ei);
    k_gnn  <<<dim3(74, T_), 256>>>(W1, b1, g1, be1, m1, v1);
    k_final<<<1, 512>>>(W2, b2, g2, be2, m2, v2, Wc, bc, (float*)d_out);
}

// round 12
// speedup vs baseline: 1.6650x; 1.1735x over previous
#include <cuda_runtime.h>
#include <cuda_bf16.h>
#include <math.h>

#define T_  8
#define N_  20000
#define E_  320000
#define DIN 64
#define H_  128
#define EPSB 1e-5f

#define SCAN_N (T_*N_)
#define SCAN_B 2048
#define NBLK ((SCAN_N + SCAN_B - 1)/SCAN_B)   // 79
#define TE (T_*E_)
#define NB 8

// ---------- scratch ----------
__device__ int           g_deg  [SCAN_N];
__device__ float         g_dinv [SCAN_N];
__device__ float         g_w2   [SCAN_N];
__device__ int           g_off  [SCAN_N + 1];
__device__ int           g_cursor[SCAN_N];
__device__ int           g_bsum [NBLK];
__device__ int           g_srcs [TE];
__device__ __nv_bfloat16 g_yb   [(size_t)SCAN_N*64];  // dinv-scaled x rows (bf16)
__device__ __nv_bfloat16 g_agg  [(size_t)SCAN_N*64];  // aggregated rows (bf16)
__device__ float         g_S    [T_*H_];
__device__ float4        g_WT4  [4][32*512];
__device__ float         g_bsumL[2][512];

// ---------- helpers ----------
__device__ __forceinline__ unsigned long long pk2(float a, float b) {
    unsigned long long r;
    asm("mov.b64 %0, {%1, %2};" : "=l"(r) : "f"(a), "f"(b));
    return r;
}
__device__ __forceinline__ unsigned long long ffma2(unsigned long long a,
                                                    unsigned long long b,
                                                    unsigned long long c) {
    unsigned long long d;
    asm("fma.rn.f32x2 %0, %1, %2, %3;" : "=l"(d) : "l"(a), "l"(b), "l"(c));
    return d;
}
__device__ __forceinline__ float2 upk2(unsigned long long v) {
    float2 f;
    asm("mov.b64 {%0, %1}, %2;" : "=f"(f.x), "=f"(f.y) : "l"(v));
    return f;
}
__device__ __forceinline__ __nv_bfloat162 asb2(unsigned u) {
    __nv_bfloat162 r; *reinterpret_cast<unsigned*>(&r) = u; return r;
}
__device__ __forceinline__ unsigned asu(__nv_bfloat162 h) {
    return *reinterpret_cast<unsigned*>(&h);
}
__device__ __forceinline__ unsigned scaleb2(unsigned a, float d) {
    float2 f = __bfloat1622float2(asb2(a));
    return asu(__floats2bfloat162_rn(f.x*d, f.y*d));
}

// sPre[b] = exclusive prefix over g_bsum[0..b)
__device__ __forceinline__ void block_prefix(int* sPre, int* sWp, int tid) {
    if (tid < 96) {
        int lane = tid & 31;
        int v = (tid < NBLK) ? g_bsum[tid] : 0;
        int incl = v;
#pragma unroll
        for (int d = 1; d < 32; d <<= 1) {
            int n = __shfl_up_sync(0xffffffffu, incl, d);
            if (lane >= d) incl += n;
        }
        if (lane == 31) sWp[tid >> 5] = incl;
        if (tid < NBLK) sPre[tid] = incl - v;
    }
    __syncthreads();
    if (tid < NBLK) {
        int w0 = tid >> 5;
        int c = 0;
        if (w0 > 0) c += sWp[0];
        if (w0 > 1) c += sWp[1];
        sPre[tid] += c;
    }
    __syncthreads();
}

// ---------- K1: in-degree count (int4) + LSTM weight prep ----------
__global__ void k_count(const int* __restrict__ ei,
                        const float* __restrict__ Wih0, const float* __restrict__ Whh0,
                        const float* __restrict__ Wih1, const float* __restrict__ Whh1,
                        const float* __restrict__ bih0, const float* __restrict__ bhh0,
                        const float* __restrict__ bih1, const float* __restrict__ bhh1) {
    int tid = threadIdx.x;
    if (blockIdx.x < 256) {
        int p = blockIdx.x * 256 + tid;
        if (p < 1024) {
            int L = p >> 9, r = p & 511;
            g_bsumL[L][r] = L ? (bih1[r] + bhh1[r]) : (bih0[r] + bhh0[r]);
        }
        int m = p >> 14, rem = p & 16383;
        int k4 = rem >> 9, r = rem & 511;
        const float* W = (m == 0) ? Wih0 : (m == 1) ? Whh0 : (m == 2) ? Wih1 : Whh1;
        g_WT4[m][k4*512 + r] = ((const float4*)W)[r*32 + k4];
    }
    int i = blockIdx.x * blockDim.x + tid;
    if (i >= TE/4) return;
    int t = i / (E_/4), e4 = i - t*(E_/4);
    int4 d4 = ((const int4*)(ei + t*2*E_ + E_))[e4];
    int base = t*N_;
    atomicAdd(&g_deg[base + d4.x], 1);
    atomicAdd(&g_deg[base + d4.y], 1);
    atomicAdd(&g_deg[base + d4.z], 1);
    atomicAdd(&g_deg[base + d4.w], 1);
}

// ---------- K2: block-local scan + dinv/w2 + bf16 y-scale + zero S ----------
__global__ void __launch_bounds__(512) k_scan1(const float* __restrict__ x) {
    __shared__ int wsum[16];
    int tid = threadIdx.x, lane = tid & 31, w = tid >> 5;
    if (blockIdx.x == 0) {
        g_S[tid] = 0.f;
        g_S[tid + 512] = 0.f;
    }
    int base = blockIdx.x*SCAN_B + tid*4;
    int v[4]; int tot = 0;
#pragma unroll
    for (int u = 0; u < 4; u++) {
        v[u] = (base + u < SCAN_N) ? g_deg[base + u] : 0;
        tot += v[u];
    }
#pragma unroll
    for (int u = 0; u < 4; u++) {
        if (base + u < SCAN_N) {
            float d = rsqrtf(1.0f + (float)v[u]);
            g_dinv[base + u] = d;
            g_w2[base + u]   = d * d;
        }
    }
    int incl = tot;
#pragma unroll
    for (int d = 1; d < 32; d <<= 1) {
        int n = __shfl_up_sync(0xffffffffu, incl, d);
        if (lane >= d) incl += n;
    }
    int excl = incl - tot;
    if (lane == 31) wsum[w] = incl;
    __syncthreads();
    if (w == 0) {
        int s = (lane < 16) ? wsum[lane] : 0;
        int inc = s;
#pragma unroll
        for (int d = 1; d < 32; d <<= 1) {
            int n = __shfl_up_sync(0xffffffffu, inc, d);
            if (lane >= d) inc += n;
        }
        if (lane < 16) wsum[lane] = inc - s;
    }
    __syncthreads();
    int run = excl + wsum[w];
#pragma unroll
    for (int u = 0; u < 4; u++) {
        if (base + u <= SCAN_N) {
            g_off[base + u] = run;
            if (base + u < SCAN_N) g_cursor[base + u] = run;
        }
        run += v[u];
    }
    if (tid == 511) g_bsum[blockIdx.x] = run;

    int nb0 = blockIdx.x*SCAN_B;
    const float4* x4 = (const float4*)x;
    for (int ci = tid; ci < SCAN_B*16; ci += 512) {
        int node = nb0 + (ci >> 4);
        if (node >= SCAN_N) break;
        float d = rsqrtf(1.0f + (float)g_deg[node]);
        float4 vv = x4[(size_t)node*16 + (ci & 15)];
        __nv_bfloat162 p0 = __floats2bfloat162_rn(d*vv.x, d*vv.y);
        __nv_bfloat162 p1 = __floats2bfloat162_rn(d*vv.z, d*vv.w);
        uint2 st; st.x = asu(p0); st.y = asu(p1);
        ((uint2*)(g_yb + (size_t)node*64))[ci & 15] = st;
    }
}

// ---------- K3: fill CSR + w2 scatter ----------
__global__ void __launch_bounds__(256) k_fill(const int* __restrict__ ei) {
    __shared__ int sPre[NBLK];
    __shared__ int sWp[3];
    int tid = threadIdx.x;
    block_prefix(sPre, sWp, tid);

    int i = blockIdx.x*256 + tid;
    if (i >= TE/4) return;
    int t = i / (E_/4), e4 = i - t*(E_/4);
    int4 s4 = ((const int4*)(ei + t*2*E_))[e4];
    int4 d4 = ((const int4*)(ei + t*2*E_ + E_))[e4];
    int base = t*N_;
#pragma unroll
    for (int u = 0; u < 4; u++) {
        int src = (u == 0) ? s4.x : (u == 1) ? s4.y : (u == 2) ? s4.z : s4.w;
        int dst = (u == 0) ? d4.x : (u == 1) ? d4.y : (u == 2) ? d4.z : d4.w;
        int ns = base + src, nd = base + dst;
        float c = g_dinv[ns] * g_dinv[nd];
        atomicAdd(&g_w2[ns], c);
        int pos = atomicAdd(&g_cursor[nd], 1) + sPre[nd >> 11];
        g_srcs[pos] = src;
    }
}

// ---------- K4: pure gather — one 8-lane group per node, bf16 agg rows ----------
__global__ void __launch_bounds__(256) k_gather() {
    __shared__ int sPre[NBLK];
    __shared__ int sWp[3];
    int tid = threadIdx.x;
    block_prefix(sPre, sWp, tid);

    int t = blockIdx.y;
    int l = tid & 7;
    const uint4* yb4 = (const uint4*)g_yb + (size_t)t*N_*8;
    uint4*       ag4 = (uint4*)g_agg       + (size_t)t*N_*8;

    for (int i = blockIdx.x*32 + (tid >> 3); i < N_; i += gridDim.x*32) {
        int node = t*N_ + i;
        uint4 sv = yb4[(size_t)i*8 + l];
        __nv_bfloat162 A0 = asb2(sv.x), A1 = asb2(sv.y),
                       A2 = asb2(sv.z), A3 = asb2(sv.w);
        int o0 = g_off[node]     + sPre[node >> 11];
        int o1 = g_off[node + 1] + sPre[(node + 1) >> 11];
#pragma unroll 4
        for (int j = o0; j < o1; j++) {
            int s = g_srcs[j];
            uint4 vv = yb4[(size_t)s*8 + l];
            A0 = __hadd2(A0, asb2(vv.x));
            A1 = __hadd2(A1, asb2(vv.y));
            A2 = __hadd2(A2, asb2(vv.z));
            A3 = __hadd2(A3, asb2(vv.w));
        }
        float ds = g_dinv[node];
        uint4 st;
        st.x = scaleb2(asu(A0), ds);
        st.y = scaleb2(asu(A1), ds);
        st.z = scaleb2(asu(A2), ds);
        st.w = scaleb2(asu(A3), ds);
        ag4[(size_t)i*8 + l] = st;
    }
}

// ---------- K5: streamed matmul (NB=8 reg-tiled) + BN1 + ReLU + weighted reduce ----------
__global__ void __launch_bounds__(256) k_mm(const float* __restrict__ W1,
                                            const float* __restrict__ b1,
                                            const float* __restrict__ g1,
                                            const float* __restrict__ be1,
                                            const float* __restrict__ m1,
                                            const float* __restrict__ v1) {
    __shared__ float2 W1p[2][DIN*32];          // 32KB
    __shared__ float  sAcc[8][4][32];
    __shared__ float  sAgg[8][NB][DIN];        // 16KB
    int tid = threadIdx.x, lane = tid & 31, w = tid >> 5;
    int t = blockIdx.y;

    for (int ii = tid; ii < 2*DIN*32; ii += 256) {
        int p = ii >> 11, rem = ii & 2047;
        int k = rem >> 5, ll = rem & 31;
        W1p[p][k*32 + ll] = make_float2(W1[k*H_ + p*64 + ll],
                                        W1[k*H_ + p*64 + ll + 32]);
    }
    float sc[4], sh[4];
#pragma unroll
    for (int q = 0; q < 4; q++) {
        int j = lane + 32*q;
        float s = g1[j] * rsqrtf(v1[j] + EPSB);
        sc[q] = s;
        sh[q] = (b1[j] - m1[j]) * s + be1[j];
    }
    __syncthreads();

    const unsigned long long* Wp0 = (const unsigned long long*)W1p[0];
    const unsigned long long* Wp1 = (const unsigned long long*)W1p[1];
    const uint4* ag4 = (const uint4*)g_agg + (size_t)t*N_*8;
    float acc[4] = {0.f, 0.f, 0.f, 0.f};

    int stride = gridDim.x * 8 * NB;
    for (int i0 = (blockIdx.x*8 + w)*NB; i0 < N_; i0 += stride) {
        // ---- load 8 rows (bf16, coalesced) into sAgg as f32 ----
#pragma unroll
        for (int cc = 0; cc < 2; cc++) {
            int chunk = lane + cc*32;           // 0..63 = 8 rows x 8 chunks
            int u = chunk >> 3, c8 = chunk & 7;
            int iu = min(i0 + u, N_ - 1);
            uint4 v = ag4[(size_t)iu*8 + c8];
            float2 f0 = __bfloat1622float2(asb2(v.x));
            float2 f1 = __bfloat1622float2(asb2(v.y));
            float2 f2 = __bfloat1622float2(asb2(v.z));
            float2 f3 = __bfloat1622float2(asb2(v.w));
            *(float4*)&sAgg[w][u][c8*8]     = make_float4(f0.x, f0.y, f1.x, f1.y);
            *(float4*)&sAgg[w][u][c8*8 + 4] = make_float4(f2.x, f2.y, f3.x, f3.y);
        }
        __syncwarp();

        // ---- NB-node register-tiled matmul ----
        unsigned long long P0[NB], P1[NB];
#pragma unroll
        for (int u = 0; u < NB; u++) { P0[u] = 0ull; P1[u] = 0ull; }
#pragma unroll 4
        for (int c = 0; c < 16; c++) {
            int k = c*4;
            unsigned long long w00 = Wp0[(k+0)*32 + lane];
            unsigned long long w01 = Wp0[(k+1)*32 + lane];
            unsigned long long w02 = Wp0[(k+2)*32 + lane];
            unsigned long long w03 = Wp0[(k+3)*32 + lane];
            unsigned long long w10 = Wp1[(k+0)*32 + lane];
            unsigned long long w11 = Wp1[(k+1)*32 + lane];
            unsigned long long w12 = Wp1[(k+2)*32 + lane];
            unsigned long long w13 = Wp1[(k+3)*32 + lane];
#pragma unroll
            for (int u = 0; u < NB; u++) {
                float4 b = *(const float4*)&sAgg[w][u][c*4];
                unsigned long long c2;
                c2 = pk2(b.x, b.x); P0[u] = ffma2(c2, w00, P0[u]);
                                    P1[u] = ffma2(c2, w10, P1[u]);
                c2 = pk2(b.y, b.y); P0[u] = ffma2(c2, w01, P0[u]);
                                    P1[u] = ffma2(c2, w11, P1[u]);
                c2 = pk2(b.z, b.z); P0[u] = ffma2(c2, w02, P0[u]);
                                    P1[u] = ffma2(c2, w12, P1[u]);
                c2 = pk2(b.w, b.w); P0[u] = ffma2(c2, w03, P0[u]);
                                    P1[u] = ffma2(c2, w13, P1[u]);
            }
        }

        // ---- epilogue ----
#pragma unroll
        for (int u = 0; u < NB; u++) {
            int iu = i0 + u;
            float wi = (iu < N_) ? g_w2[t*N_ + iu] : 0.f;
            float2 y01 = upk2(P0[u]), y23 = upk2(P1[u]);
            acc[0] += wi * fmaxf(y01.x*sc[0] + sh[0], 0.f);
            acc[1] += wi * fmaxf(y01.y*sc[1] + sh[1], 0.f);
            acc[2] += wi * fmaxf(y23.x*sc[2] + sh[2], 0.f);
            acc[3] += wi * fmaxf(y23.y*sc[3] + sh[3], 0.f);
        }
        __syncwarp();
    }
#pragma unroll
    for (int q = 0; q < 4; q++) sAcc[w][q][lane] = acc[q];
    __syncthreads();
    if (tid < 128) {
        int q = tid >> 5, ll = tid & 31;
        float s = 0.f;
#pragma unroll
        for (int ww = 0; ww < 8; ww++) s += sAcc[ww][q][ll];
        atomicAdd(&g_S[t*H_ + q*32 + ll], s);
    }
}

__device__ __forceinline__ float sigf(float x) { return 1.f / (1.f + expf(-x)); }

// ---------- K6: finalize ----------
__global__ void __launch_bounds__(512) k_final(const float* __restrict__ W2,
                                               const float* __restrict__ b2,
                                               const float* __restrict__ g2,
                                               const float* __restrict__ be2,
                                               const float* __restrict__ m2,
                                               const float* __restrict__ v2,
                                               const float* __restrict__ Wc,
                                               const float* __restrict__ bc,
                                               float* __restrict__ out) {
    __shared__ float Ssm[T_*H_];
    __shared__ float emb[T_][H_];
    __shared__ float h0[H_], c0[H_], h1[H_], c1[H_];
    __shared__ float gates[512];
    int tid = threadIdx.x;

    for (int i = tid; i < T_*H_; i += 512) Ssm[i] = g_S[i] * (1.0f / N_);
    if (tid < H_) { h0[tid] = 0.f; c0[tid] = 0.f; h1[tid] = 0.f; c1[tid] = 0.f; }
    __syncthreads();

    for (int item = tid; item < T_*H_; item += 512) {
        int t = item >> 7, j = item & 127;
        float s2  = g2[j] * rsqrtf(v2[j] + EPSB);
        float sh2 = be2[j] - m2[j]*s2;
        float acc = b2[j];
#pragma unroll 8
        for (int k = 0; k < H_; k++) acc += Ssm[t*H_ + k] * W2[k*H_ + j];
        emb[t][j] = acc*s2 + sh2;
    }
    __syncthreads();

    int r = tid;
    for (int t = 0; t < T_; t++) {
        float acc = g_bsumL[0][r];
#pragma unroll 8
        for (int k4 = 0; k4 < 32; k4++) {
            float4 wx = g_WT4[0][k4*512 + r];
            float4 wh = g_WT4[1][k4*512 + r];
            int k = k4*4;
            acc += wx.x*emb[t][k] + wx.y*emb[t][k+1] + wx.z*emb[t][k+2] + wx.w*emb[t][k+3];
            acc += wh.x*h0[k]     + wh.y*h0[k+1]     + wh.z*h0[k+2]     + wh.w*h0[k+3];
        }
        gates[r] = acc;
        __syncthreads();
        if (tid < H_) {
            int j = tid;
            float ig = sigf(gates[j]);
            float fg = sigf(gates[H_ + j]);
            float gg = tanhf(gates[2*H_ + j]);
            float og = sigf(gates[3*H_ + j]);
            float cn = fg*c0[j] + ig*gg;
            c0[j] = cn;
            h0[j] = og * tanhf(cn);
        }
        __syncthreads();
        acc = g_bsumL[1][r];
#pragma unroll 8
        for (int k4 = 0; k4 < 32; k4++) {
            float4 wx = g_WT4[2][k4*512 + r];
            float4 wh = g_WT4[3][k4*512 + r];
            int k = k4*4;
            acc += wx.x*h0[k] + wx.y*h0[k+1] + wx.z*h0[k+2] + wx.w*h0[k+3];
            acc += wh.x*h1[k] + wh.y*h1[k+1] + wh.z*h1[k+2] + wh.w*h1[k+3];
        }
        gates[r] = acc;
        __syncthreads();
        if (tid < H_) {
            int j = tid;
            float ig = sigf(gates[j]);
            float fg = sigf(gates[H_ + j]);
            float gg = tanhf(gates[2*H_ + j]);
            float og = sigf(gates[3*H_ + j]);
            float cn = fg*c1[j] + ig*gg;
            c1[j] = cn;
            h1[j] = og * tanhf(cn);
        }
        __syncthreads();
    }

    if (tid < 2) {
        float acc = bc[tid];
#pragma unroll 8
        for (int k = 0; k < H_; k++) acc += Wc[tid*H_ + k] * h1[k];
        out[tid] = acc;
    }
    if (tid < H_) out[2 + tid] = h1[tid];
}

// ---------- launch ----------
extern "C" void kernel_launch(void* const* d_in, const int* in_sizes, int n_in,
                              void* d_out, int out_size) {
    const float* x    = (const float*)d_in[0];
    const int*   ei   = (const int*)  d_in[1];
    const float* W1   = (const float*)d_in[2];
    const float* b1   = (const float*)d_in[3];
    const float* g1   = (const float*)d_in[4];
    const float* be1  = (const float*)d_in[5];
    const float* m1   = (const float*)d_in[6];
    const float* v1   = (const float*)d_in[7];
    const float* W2   = (const float*)d_in[8];
    const float* b2   = (const float*)d_in[9];
    const float* g2   = (const float*)d_in[10];
    const float* be2  = (const float*)d_in[11];
    const float* m2   = (const float*)d_in[12];
    const float* v2   = (const float*)d_in[13];
    const float* Wih0 = (const float*)d_in[14];
    const float* Whh0 = (const float*)d_in[15];
    const float* bih0 = (const float*)d_in[16];
    const float* bhh0 = (const float*)d_in[17];
    const float* Wih1 = (const float*)d_in[18];
    const float* Whh1 = (const float*)d_in[19];
    const float* bih1 = (const float*)d_in[20];
    const float* bhh1 = (const float*)d_in[21];
    const float* Wc   = (const float*)d_in[22];
    const float* bc   = (const float*)d_in[23];

    void* degp = nullptr;
    cudaGetSymbolAddress(&degp, g_deg);
    cudaMemsetAsync(degp, 0, SCAN_N * sizeof(int));

    k_count <<<(TE/4 + 255)/256, 256>>>(ei, Wih0, Whh0, Wih1, Whh1,
                                        bih0, bhh0, bih1, bhh1);
    k_scan1 <<<NBLK, 512>>>(x);
    k_fill  <<<(TE/4 + 255)/256, 256>>>(ei);
    k_gather<<<dim3(148, T_), 256>>>();
    k_mm    <<<dim3(74, T_), 256>>>(W1, b1, g1, be1, m1, v1);
    k_final <<<1, 512>>>(W2, b2, g2, be2, m2, v2, Wc, bc, (float*)d_out);
}

// round 13
// speedup vs baseline: 1.9164x; 1.1510x over previous
#include <cuda_runtime.h>
#include <cuda_bf16.h>
#include <math.h>

#define T_  8
#define N_  20000
#define E_  320000
#define DIN 64
#define H_  128
#define EPSB 1e-5f

#define SCAN_N (T_*N_)
#define TE (T_*E_)
#define NB 8
#define CAP 64          // bucket capacity per node (P(deg>64) ~ 1e-20)

// ---------- scratch ----------
__device__ float         g_dinv [SCAN_N];
__device__ float         g_w2   [SCAN_N];
__device__ int           g_cursor[SCAN_N];
__device__ int           g_bkt  [(size_t)SCAN_N*CAP];   // 41MB
__device__ __nv_bfloat16 g_yb   [(size_t)SCAN_N*64];
__device__ __nv_bfloat16 g_agg  [(size_t)SCAN_N*64];
__device__ float         g_S    [T_*H_];
__device__ float4        g_WT4  [4][32*512];
__device__ float         g_bsumL[2][512];

// ---------- helpers ----------
__device__ __forceinline__ unsigned long long pk2(float a, float b) {
    unsigned long long r;
    asm("mov.b64 %0, {%1, %2};" : "=l"(r) : "f"(a), "f"(b));
    return r;
}
__device__ __forceinline__ unsigned long long ffma2(unsigned long long a,
                                                    unsigned long long b,
                                                    unsigned long long c) {
    unsigned long long d;
    asm("fma.rn.f32x2 %0, %1, %2, %3;" : "=l"(d) : "l"(a), "l"(b), "l"(c));
    return d;
}
__device__ __forceinline__ float2 upk2(unsigned long long v) {
    float2 f;
    asm("mov.b64 {%0, %1}, %2;" : "=f"(f.x), "=f"(f.y) : "l"(v));
    return f;
}
__device__ __forceinline__ __nv_bfloat162 asb2(unsigned u) {
    __nv_bfloat162 r; *reinterpret_cast<unsigned*>(&r) = u; return r;
}
__device__ __forceinline__ unsigned asu(__nv_bfloat162 h) {
    return *reinterpret_cast<unsigned*>(&h);
}
__device__ __forceinline__ unsigned scaleb2(unsigned a, float d) {
    float2 f = __bfloat1622float2(asb2(a));
    return asu(__floats2bfloat162_rn(f.x*d, f.y*d));
}

// ---------- K1: single-pass bucket fill + LSTM weight prep ----------
__global__ void __launch_bounds__(256) k_fillb(const int* __restrict__ ei,
                        const float* __restrict__ Wih0, const float* __restrict__ Whh0,
                        const float* __restrict__ Wih1, const float* __restrict__ Whh1,
                        const float* __restrict__ bih0, const float* __restrict__ bhh0,
                        const float* __restrict__ bih1, const float* __restrict__ bhh1) {
    int tid = threadIdx.x;
    if (blockIdx.x < 256) {
        int p = blockIdx.x * 256 + tid;              // 0..65535
        if (p < 1024) {
            int L = p >> 9, r = p & 511;
            g_bsumL[L][r] = L ? (bih1[r] + bhh1[r]) : (bih0[r] + bhh0[r]);
        }
        int m = p >> 14, rem = p & 16383;
        int k4 = rem >> 9, r = rem & 511;
        const float* W = (m == 0) ? Wih0 : (m == 1) ? Whh0 : (m == 2) ? Wih1 : Whh1;
        g_WT4[m][k4*512 + r] = ((const float4*)W)[r*32 + k4];
    }
    int i = blockIdx.x * 256 + tid;
    if (i >= TE/4) return;
    int t = i / (E_/4), e4 = i - t*(E_/4);
    int4 s4 = ((const int4*)(ei + t*2*E_))[e4];
    int4 d4 = ((const int4*)(ei + t*2*E_ + E_))[e4];
    int base = t*N_;
#pragma unroll
    for (int u = 0; u < 4; u++) {
        int src = (u == 0) ? s4.x : (u == 1) ? s4.y : (u == 2) ? s4.z : s4.w;
        int dst = (u == 0) ? d4.x : (u == 1) ? d4.y : (u == 2) ? d4.z : d4.w;
        int nd = base + dst;
        int pos = atomicAdd(&g_cursor[nd], 1);
        if (pos < CAP) g_bkt[(size_t)nd*CAP + pos] = src;
    }
}

// ---------- K2: dinv/w2-self + bf16 y-scale + zero S ----------
__global__ void __launch_bounds__(512) k_prep(const float* __restrict__ x) {
    int tid = threadIdx.x;
    if (blockIdx.x == 0 && tid < T_*H_) {
        g_S[tid] = 0.f;
        g_S[tid + 512] = 0.f;
    }
    int i = blockIdx.x*512 + tid;                    // over SCAN_N*16
    if (i >= SCAN_N*16) return;
    int node = i >> 4;
    float d = rsqrtf(1.0f + (float)g_cursor[node]);
    if ((i & 15) == 0) {
        g_dinv[node] = d;
        g_w2[node]   = d * d;                        // self term; edges added in gather
    }
    float4 vv = ((const float4*)x)[i];
    __nv_bfloat162 p0 = __floats2bfloat162_rn(d*vv.x, d*vv.y);
    __nv_bfloat162 p1 = __floats2bfloat162_rn(d*vv.z, d*vv.w);
    uint2 st; st.x = asu(p0); st.y = asu(p1);
    ((uint2*)(g_yb + (size_t)node*64))[i & 15] = st;
}

// ---------- K3: gather (8 lanes/node) + w2 edge REDG ----------
__global__ void __launch_bounds__(256) k_gather() {
    int tid = threadIdx.x;
    int t = blockIdx.y;
    int l = tid & 7;
    const uint4* yb4 = (const uint4*)g_yb + (size_t)t*N_*8;
    uint4*       ag4 = (uint4*)g_agg      + (size_t)t*N_*8;

    for (int i = blockIdx.x*32 + (tid >> 3); i < N_; i += gridDim.x*32) {
        int node = t*N_ + i;
        int cnt = min(g_cursor[node], CAP);
        const int* bp = g_bkt + (size_t)node*CAP;
        float dd = g_dinv[node];

        // w2 edge terms: lanes partition edges; REDG to src
        for (int j = l; j < cnt; j += 8) {
            int s = bp[j];
            float ds_ = g_dinv[t*N_ + s];
            atomicAdd(&g_w2[t*N_ + s], ds_ * dd);
        }

        // feature aggregation (broadcast src per edge, lane = chunk)
        uint4 sv = yb4[(size_t)i*8 + l];
        __nv_bfloat162 A0 = asb2(sv.x), A1 = asb2(sv.y),
                       A2 = asb2(sv.z), A3 = asb2(sv.w);
#pragma unroll 4
        for (int j = 0; j < cnt; j++) {
            int s = bp[j];
            uint4 vv = yb4[(size_t)s*8 + l];
            A0 = __hadd2(A0, asb2(vv.x));
            A1 = __hadd2(A1, asb2(vv.y));
            A2 = __hadd2(A2, asb2(vv.z));
            A3 = __hadd2(A3, asb2(vv.w));
        }
        uint4 st;
        st.x = scaleb2(asu(A0), dd);
        st.y = scaleb2(asu(A1), dd);
        st.z = scaleb2(asu(A2), dd);
        st.w = scaleb2(asu(A3), dd);
        ag4[(size_t)i*8 + l] = st;
    }
}

// ---------- K4 (PROFILE SLOT): streamed NB=8 reg-tiled matmul + BN1 + ReLU + weighted reduce ----------
__global__ void __launch_bounds__(256) k_mm(const float* __restrict__ W1,
                                            const float* __restrict__ b1,
                                            const float* __restrict__ g1,
                                            const float* __restrict__ be1,
                                            const float* __restrict__ m1,
                                            const float* __restrict__ v1) {
    __shared__ float2 W1p[2][DIN*32];
    __shared__ float  sAcc[8][4][32];
    __shared__ float  sAgg[8][NB][DIN];
    int tid = threadIdx.x, lane = tid & 31, w = tid >> 5;
    int t = blockIdx.y;

    for (int ii = tid; ii < 2*DIN*32; ii += 256) {
        int p = ii >> 11, rem = ii & 2047;
        int k = rem >> 5, ll = rem & 31;
        W1p[p][k*32 + ll] = make_float2(W1[k*H_ + p*64 + ll],
                                        W1[k*H_ + p*64 + ll + 32]);
    }
    float sc[4], sh[4];
#pragma unroll
    for (int q = 0; q < 4; q++) {
        int j = lane + 32*q;
        float s = g1[j] * rsqrtf(v1[j] + EPSB);
        sc[q] = s;
        sh[q] = (b1[j] - m1[j]) * s + be1[j];
    }
    __syncthreads();

    const unsigned long long* Wp0 = (const unsigned long long*)W1p[0];
    const unsigned long long* Wp1 = (const unsigned long long*)W1p[1];
    const uint4* ag4 = (const uint4*)g_agg + (size_t)t*N_*8;
    float acc[4] = {0.f, 0.f, 0.f, 0.f};

    int stride = gridDim.x * 8 * NB;
    for (int i0 = (blockIdx.x*8 + w)*NB; i0 < N_; i0 += stride) {
#pragma unroll
        for (int cc = 0; cc < 2; cc++) {
            int chunk = lane + cc*32;
            int u = chunk >> 3, c8 = chunk & 7;
            int iu = min(i0 + u, N_ - 1);
            uint4 v = ag4[(size_t)iu*8 + c8];
            float2 f0 = __bfloat1622float2(asb2(v.x));
            float2 f1 = __bfloat1622float2(asb2(v.y));
            float2 f2 = __bfloat1622float2(asb2(v.z));
            float2 f3 = __bfloat1622float2(asb2(v.w));
            *(float4*)&sAgg[w][u][c8*8]     = make_float4(f0.x, f0.y, f1.x, f1.y);
            *(float4*)&sAgg[w][u][c8*8 + 4] = make_float4(f2.x, f2.y, f3.x, f3.y);
        }
        __syncwarp();

        unsigned long long P0[NB], P1[NB];
#pragma unroll
        for (int u = 0; u < NB; u++) { P0[u] = 0ull; P1[u] = 0ull; }
#pragma unroll 4
        for (int c = 0; c < 16; c++) {
            int k = c*4;
            unsigned long long w00 = Wp0[(k+0)*32 + lane];
            unsigned long long w01 = Wp0[(k+1)*32 + lane];
            unsigned long long w02 = Wp0[(k+2)*32 + lane];
            unsigned long long w03 = Wp0[(k+3)*32 + lane];
            unsigned long long w10 = Wp1[(k+0)*32 + lane];
            unsigned long long w11 = Wp1[(k+1)*32 + lane];
            unsigned long long w12 = Wp1[(k+2)*32 + lane];
            unsigned long long w13 = Wp1[(k+3)*32 + lane];
#pragma unroll
            for (int u = 0; u < NB; u++) {
                float4 b = *(const float4*)&sAgg[w][u][c*4];
                unsigned long long c2;
                c2 = pk2(b.x, b.x); P0[u] = ffma2(c2, w00, P0[u]);
                                    P1[u] = ffma2(c2, w10, P1[u]);
                c2 = pk2(b.y, b.y); P0[u] = ffma2(c2, w01, P0[u]);
                                    P1[u] = ffma2(c2, w11, P1[u]);
                c2 = pk2(b.z, b.z); P0[u] = ffma2(c2, w02, P0[u]);
                                    P1[u] = ffma2(c2, w12, P1[u]);
                c2 = pk2(b.w, b.w); P0[u] = ffma2(c2, w03, P0[u]);
                                    P1[u] = ffma2(c2, w13, P1[u]);
            }
        }

#pragma unroll
        for (int u = 0; u < NB; u++) {
            int iu = i0 + u;
            float wi = (iu < N_) ? g_w2[t*N_ + iu] : 0.f;
            float2 y01 = upk2(P0[u]), y23 = upk2(P1[u]);
            acc[0] += wi * fmaxf(y01.x*sc[0] + sh[0], 0.f);
            acc[1] += wi * fmaxf(y01.y*sc[1] + sh[1], 0.f);
            acc[2] += wi * fmaxf(y23.x*sc[2] + sh[2], 0.f);
            acc[3] += wi * fmaxf(y23.y*sc[3] + sh[3], 0.f);
        }
        __syncwarp();
    }
#pragma unroll
    for (int q = 0; q < 4; q++) sAcc[w][q][lane] = acc[q];
    __syncthreads();
    if (tid < 128) {
        int q = tid >> 5, ll = tid & 31;
        float s = 0.f;
#pragma unroll
        for (int ww = 0; ww < 8; ww++) s += sAcc[ww][q][ll];
        atomicAdd(&g_S[t*H_ + q*32 + ll], s);
    }
}

__device__ __forceinline__ float sigf(float x) { return 1.f / (1.f + expf(-x)); }

// ---------- K5: finalize ----------
__global__ void __launch_bounds__(512) k_final(const float* __restrict__ W2,
                                               const float* __restrict__ b2,
                                               const float* __restrict__ g2,
                                               const float* __restrict__ be2,
                                               const float* __restrict__ m2,
                                               const float* __restrict__ v2,
                                               const float* __restrict__ Wc,
                                               const float* __restrict__ bc,
                                               float* __restrict__ out) {
    __shared__ float Ssm[T_*H_];
    __shared__ float emb[T_][H_];
    __shared__ float h0[H_], c0[H_], h1[H_], c1[H_];
    __shared__ float gates[512];
    int tid = threadIdx.x;

    for (int i = tid; i < T_*H_; i += 512) Ssm[i] = g_S[i] * (1.0f / N_);
    if (tid < H_) { h0[tid] = 0.f; c0[tid] = 0.f; h1[tid] = 0.f; c1[tid] = 0.f; }
    __syncthreads();

    for (int item = tid; item < T_*H_; item += 512) {
        int t = item >> 7, j = item & 127;
        float s2  = g2[j] * rsqrtf(v2[j] + EPSB);
        float sh2 = be2[j] - m2[j]*s2;
        float acc = b2[j];
#pragma unroll 8
        for (int k = 0; k < H_; k++) acc += Ssm[t*H_ + k] * W2[k*H_ + j];
        emb[t][j] = acc*s2 + sh2;
    }
    __syncthreads();

    int r = tid;
    for (int t = 0; t < T_; t++) {
        float acc = g_bsumL[0][r];
#pragma unroll 8
        for (int k4 = 0; k4 < 32; k4++) {
            float4 wx = g_WT4[0][k4*512 + r];
            float4 wh = g_WT4[1][k4*512 + r];
            int k = k4*4;
            acc += wx.x*emb[t][k] + wx.y*emb[t][k+1] + wx.z*emb[t][k+2] + wx.w*emb[t][k+3];
            acc += wh.x*h0[k]     + wh.y*h0[k+1]     + wh.z*h0[k+2]     + wh.w*h0[k+3];
        }
        gates[r] = acc;
        __syncthreads();
        if (tid < H_) {
            int j = tid;
            float ig = sigf(gates[j]);
            float fg = sigf(gates[H_ + j]);
            float gg = tanhf(gates[2*H_ + j]);
            float og = sigf(gates[3*H_ + j]);
            float cn = fg*c0[j] + ig*gg;
            c0[j] = cn;
            h0[j] = og * tanhf(cn);
        }
        __syncthreads();
        acc = g_bsumL[1][r];
#pragma unroll 8
        for (int k4 = 0; k4 < 32; k4++) {
            float4 wx = g_WT4[2][k4*512 + r];
            float4 wh = g_WT4[3][k4*512 + r];
            int k = k4*4;
            acc += wx.x*h0[k] + wx.y*h0[k+1] + wx.z*h0[k+2] + wx.w*h0[k+3];
            acc += wh.x*h1[k] + wh.y*h1[k+1] + wh.z*h1[k+2] + wh.w*h1[k+3];
        }
        gates[r] = acc;
        __syncthreads();
        if (tid < H_) {
            int j = tid;
            float ig = sigf(gates[j]);
            float fg = sigf(gates[H_ + j]);
            float gg = tanhf(gates[2*H_ + j]);
            float og = sigf(gates[3*H_ + j]);
            float cn = fg*c1[j] + ig*gg;
            c1[j] = cn;
            h1[j] = og * tanhf(cn);
        }
        __syncthreads();
    }

    if (tid < 2) {
        float acc = bc[tid];
#pragma unroll 8
        for (int k = 0; k < H_; k++) acc += Wc[tid*H_ + k] * h1[k];
        out[tid] = acc;
    }
    if (tid < H_) out[2 + tid] = h1[tid];
}

// ---------- launch ----------
extern "C" void kernel_launch(void* const* d_in, const int* in_sizes, int n_in,
                              void* d_out, int out_size) {
    const float* x    = (const float*)d_in[0];
    const int*   ei   = (const int*)  d_in[1];
    const float* W1   = (const float*)d_in[2];
    const float* b1   = (const float*)d_in[3];
    const float* g1   = (const float*)d_in[4];
    const float* be1  = (const float*)d_in[5];
    const float* m1   = (const float*)d_in[6];
    const float* v1   = (const float*)d_in[7];
    const float* W2   = (const float*)d_in[8];
    const float* b2   = (const float*)d_in[9];
    const float* g2   = (const float*)d_in[10];
    const float* be2  = (const float*)d_in[11];
    const float* m2   = (const float*)d_in[12];
    const float* v2   = (const float*)d_in[13];
    const float* Wih0 = (const float*)d_in[14];
    const float* Whh0 = (const float*)d_in[15];
    const float* bih0 = (const float*)d_in[16];
    const float* bhh0 = (const float*)d_in[17];
    const float* Wih1 = (const float*)d_in[18];
    const float* Whh1 = (const float*)d_in[19];
    const float* bih1 = (const float*)d_in[20];
    const float* bhh1 = (const float*)d_in[21];
    const float* Wc   = (const float*)d_in[22];
    const float* bc   = (const float*)d_in[23];

    void* curp = nullptr;
    cudaGetSymbolAddress(&curp, g_cursor);
    cudaMemsetAsync(curp, 0, SCAN_N * sizeof(int));

    k_fillb <<<(TE/4 + 255)/256, 256>>>(ei, Wih0, Whh0, Wih1, Whh1,
                                        bih0, bhh0, bih1, bhh1);
    k_prep  <<<(SCAN_N*16 + 511)/512, 512>>>(x);
    k_gather<<<dim3(148, T_), 256>>>();
    k_mm    <<<dim3(74, T_), 256>>>(W1, b1, g1, be1, m1, v1);
    k_final <<<1, 512>>>(W2, b2, g2, be2, m2, v2, Wc, bc, (float*)d_out);
}